// round 1
// baseline (speedup 1.0000x reference)
#include <cuda_runtime.h>

// ---------------------------------------------------------------------------
// DAGCondGNNEncoder: GatedGCN-style layer, V=50000, E=625000, H=128.
//   Uh=h@WU+bU; Vn=h@WV+bV; Ah=h@WA+bA; Bh=h@WB+bB       (node GEMMs)
//   e_pre = Ah[col] + Bh[row] + (e@WC+bC)                 (edge GEMM + gathers)
//   agg[row] += sigmoid(e_pre) * Vn[col]                  (scatter)
//   x_out = h + relu(BN(Uh+agg))
//   e_out = e + relu(BN(e_pre))@Wo + ((time@Wt+bt)@Wo+bo)
// BN = batch stats over axis 0, biased var, eps=1e-5.
// ---------------------------------------------------------------------------

#define H 128
#define VMAX 50000
#define EMAX 625000

typedef unsigned long long ull;

// scratch (device globals: allocation-free rule)
__device__ __align__(16) float g_agg[(size_t)VMAX * H];   // Uh, then += scatter
__device__ __align__(16) float g_Vn [(size_t)VMAX * H];
__device__ __align__(16) float g_Ah [(size_t)VMAX * H];
__device__ __align__(16) float g_Bh [(size_t)VMAX * H];
__device__ __align__(16) float g_epre[(size_t)EMAX * H];
__device__ __align__(16) float g_stats[4 * H];            // sum_h, sq_h, sum_e, sq_e
__device__ __align__(16) float g_cvec[H];                 // (time@Wt+bt)@Wo + bo
__device__ __align__(16) float g_scale_h[H];
__device__ __align__(16) float g_shift_h[H];
__device__ __align__(16) float g_scale_e[H];
__device__ __align__(16) float g_shift_e[H];

// ---- packed f32x2 helpers (FFMA2: 2x fp32 FMA throughput on sm_100+) ----
__device__ __forceinline__ ull pk2(float x, float y) {
    ull r; asm("mov.b64 %0, {%1, %2};" : "=l"(r) : "f"(x), "f"(y)); return r;
}
__device__ __forceinline__ void fma2(ull& d, ull a, ull b) {
    asm("fma.rn.f32x2 %0, %1, %2, %0;" : "+l"(d) : "l"(a), "l"(b));
}
__device__ __forceinline__ void up2(ull u, float& x, float& y) {
    asm("mov.b64 {%0, %1}, %2;" : "=f"(x), "=f"(y) : "l"(u));
}

// ---- shared GEMM tile core: BM=64, BN=128, BK=16, 256 thr, 4x8 per thread ----
__device__ __forceinline__ void mm_step(const float (*As)[64], const float (*Bs)[128],
                                        ull acc[4][4], int ty, int tx) {
#pragma unroll
    for (int k = 0; k < 16; k++) {
        float4 a  = *(const float4*)&As[k][ty * 4];
        float4 b0 = *(const float4*)&Bs[k][tx * 8];
        float4 b1 = *(const float4*)&Bs[k][tx * 8 + 4];
        ull bp0 = pk2(b0.x, b0.y), bp1 = pk2(b0.z, b0.w);
        ull bp2 = pk2(b1.x, b1.y), bp3 = pk2(b1.z, b1.w);
        ull a0 = pk2(a.x, a.x), a1 = pk2(a.y, a.y);
        ull a2 = pk2(a.z, a.z), a3 = pk2(a.w, a.w);
        fma2(acc[0][0], a0, bp0); fma2(acc[0][1], a0, bp1);
        fma2(acc[0][2], a0, bp2); fma2(acc[0][3], a0, bp3);
        fma2(acc[1][0], a1, bp0); fma2(acc[1][1], a1, bp1);
        fma2(acc[1][2], a1, bp2); fma2(acc[1][3], a1, bp3);
        fma2(acc[2][0], a2, bp0); fma2(acc[2][1], a2, bp1);
        fma2(acc[2][2], a2, bp2); fma2(acc[2][3], a2, bp3);
        fma2(acc[3][0], a3, bp0); fma2(acc[3][1], a3, bp1);
        fma2(acc[3][2], a3, bp2); fma2(acc[3][3], a3, bp3);
    }
}

__device__ __forceinline__ void unpack_row(const ull* accrow, float* c8) {
    up2(accrow[0], c8[0], c8[1]); up2(accrow[1], c8[2], c8[3]);
    up2(accrow[2], c8[4], c8[5]); up2(accrow[3], c8[6], c8[7]);
}

// ---------------------------------------------------------------------------
// k_init: zero BN accumulators; compute cvec = (time@Wt+bt)@Wo + bo
// ---------------------------------------------------------------------------
__global__ void k_init(const float* __restrict__ time_emb,
                       const float* __restrict__ Wt, const float* __restrict__ bt,
                       const float* __restrict__ Wo, const float* __restrict__ bo) {
    int j = threadIdx.x;  // 128 threads
    for (int i = j; i < 4 * H; i += H) g_stats[i] = 0.0f;
    __shared__ float tv[H];
    float acc = bt[j];
    for (int k = 0; k < H; k++) acc += time_emb[k] * Wt[k * H + j];
    tv[j] = acc;
    __syncthreads();
    float c = bo[j];
    for (int k = 0; k < H; k++) c += tv[k] * Wo[k * H + j];
    g_cvec[j] = c;
}

// ---------------------------------------------------------------------------
// k_node: fused 4-weight node GEMM. blockIdx.y picks {WU->agg, WV->Vn, WA->Ah, WB->Bh}
// ---------------------------------------------------------------------------
__global__ __launch_bounds__(256) void k_node(
        const float* __restrict__ h,
        const float* __restrict__ WU, const float* __restrict__ bU,
        const float* __restrict__ WV, const float* __restrict__ bV,
        const float* __restrict__ WA, const float* __restrict__ bA,
        const float* __restrict__ WB, const float* __restrict__ bB,
        int V) {
    __shared__ float As[16][64];
    __shared__ float Bs[16][128];
    __shared__ float bS[128];

    const float* W; const float* bias; float* out;
    switch (blockIdx.y) {
        case 0:  W = WU; bias = bU; out = g_agg; break;
        case 1:  W = WV; bias = bV; out = g_Vn;  break;
        case 2:  W = WA; bias = bA; out = g_Ah;  break;
        default: W = WB; bias = bB; out = g_Bh;  break;
    }
    int tid = threadIdx.x;
    if (tid < 128) bS[tid] = bias[tid];

    int row0 = blockIdx.x * 64;
    int ty = tid >> 4, tx = tid & 15;
    ull acc[4][4] = {};

    for (int kk = 0; kk < H; kk += 16) {
        int m = tid >> 2, kq = (tid & 3) * 4;
        int row = row0 + m;
        float4 av = make_float4(0.f, 0.f, 0.f, 0.f);
        if (row < V) av = *(const float4*)&h[(size_t)row * H + kk + kq];
        As[kq][m] = av.x; As[kq + 1][m] = av.y; As[kq + 2][m] = av.z; As[kq + 3][m] = av.w;
#pragma unroll
        for (int f = tid; f < 512; f += 256) {
            int k = f >> 5, j = (f & 31) * 4;
            *(float4*)&Bs[k][j] = *(const float4*)&W[(size_t)(kk + k) * H + j];
        }
        __syncthreads();
        mm_step(As, Bs, acc, ty, tx);
        __syncthreads();
    }

    int j0 = tx * 8;
#pragma unroll
    for (int i = 0; i < 4; i++) {
        int row = row0 + ty * 4 + i;
        if (row >= V) continue;
        float c8[8]; unpack_row(acc[i], c8);
        float4 o0 = make_float4(c8[0] + bS[j0], c8[1] + bS[j0 + 1], c8[2] + bS[j0 + 2], c8[3] + bS[j0 + 3]);
        float4 o1 = make_float4(c8[4] + bS[j0 + 4], c8[5] + bS[j0 + 5], c8[6] + bS[j0 + 6], c8[7] + bS[j0 + 7]);
        *(float4*)&out[(size_t)row * H + j0]     = o0;
        *(float4*)&out[(size_t)row * H + j0 + 4] = o1;
    }
}

// ---------------------------------------------------------------------------
// k_edge: Ce = e@WC + bC; e_pre = Ce + Ah[col] + Bh[row]; store e_pre;
//         agg[row] += sigmoid(e_pre)*Vn[col]; accumulate BN stats for e.
// ---------------------------------------------------------------------------
__global__ __launch_bounds__(256) void k_edge(
        const float* __restrict__ e,
        const float* __restrict__ WC, const float* __restrict__ bC,
        const int* __restrict__ eidx, int E) {
    __shared__ float As[16][64];
    __shared__ float Bs[16][128];
    __shared__ float red[16][128];
    __shared__ int rI[64], cI[64];
    __shared__ float bCs[128];

    int tid = threadIdx.x;
    int e0 = blockIdx.x * 64;
    if (tid < 64) {
        int ei = e0 + tid;
        rI[tid] = (ei < E) ? eidx[ei] : 0;
        cI[tid] = (ei < E) ? eidx[E + ei] : 0;
    }
    if (tid < 128) bCs[tid] = bC[tid];

    int ty = tid >> 4, tx = tid & 15;
    ull acc[4][4] = {};

    for (int kk = 0; kk < H; kk += 16) {
        int m = tid >> 2, kq = (tid & 3) * 4;
        int row = e0 + m;
        float4 av = make_float4(0.f, 0.f, 0.f, 0.f);
        if (row < E) av = *(const float4*)&e[(size_t)row * H + kk + kq];
        As[kq][m] = av.x; As[kq + 1][m] = av.y; As[kq + 2][m] = av.z; As[kq + 3][m] = av.w;
#pragma unroll
        for (int f = tid; f < 512; f += 256) {
            int k = f >> 5, j = (f & 31) * 4;
            *(float4*)&Bs[k][j] = *(const float4*)&WC[(size_t)(kk + k) * H + j];
        }
        __syncthreads();
        mm_step(As, Bs, acc, ty, tx);
        __syncthreads();
    }

    int j0 = tx * 8;
    float lsum[8] = {0.f, 0.f, 0.f, 0.f, 0.f, 0.f, 0.f, 0.f};
    float lsq[8]  = {0.f, 0.f, 0.f, 0.f, 0.f, 0.f, 0.f, 0.f};

#pragma unroll
    for (int i = 0; i < 4; i++) {
        int m = ty * 4 + i;
        int ei = e0 + m;
        if (ei >= E) continue;
        float c8[8]; unpack_row(acc[i], c8);
        int rv = rI[m], cv = cI[m];
        const float* ahp = &g_Ah[(size_t)cv * H + j0];
        const float* bhp = &g_Bh[(size_t)rv * H + j0];
        float4 ah0 = *(const float4*)ahp,        ah1 = *(const float4*)(ahp + 4);
        float4 bh0 = *(const float4*)bhp,        bh1 = *(const float4*)(bhp + 4);
        float ep[8];
        ep[0] = c8[0] + bCs[j0 + 0] + ah0.x + bh0.x;
        ep[1] = c8[1] + bCs[j0 + 1] + ah0.y + bh0.y;
        ep[2] = c8[2] + bCs[j0 + 2] + ah0.z + bh0.z;
        ep[3] = c8[3] + bCs[j0 + 3] + ah0.w + bh0.w;
        ep[4] = c8[4] + bCs[j0 + 4] + ah1.x + bh1.x;
        ep[5] = c8[5] + bCs[j0 + 5] + ah1.y + bh1.y;
        ep[6] = c8[6] + bCs[j0 + 6] + ah1.z + bh1.z;
        ep[7] = c8[7] + bCs[j0 + 7] + ah1.w + bh1.w;

        *(float4*)&g_epre[(size_t)ei * H + j0]     = make_float4(ep[0], ep[1], ep[2], ep[3]);
        *(float4*)&g_epre[(size_t)ei * H + j0 + 4] = make_float4(ep[4], ep[5], ep[6], ep[7]);

        const float* vnp = &g_Vn[(size_t)cv * H + j0];
        float4 vn0 = *(const float4*)vnp, vn1 = *(const float4*)(vnp + 4);
        float vn[8] = {vn0.x, vn0.y, vn0.z, vn0.w, vn1.x, vn1.y, vn1.z, vn1.w};
        float* aggp = &g_agg[(size_t)rv * H + j0];
#pragma unroll
        for (int q = 0; q < 8; q++) {
            float x = ep[q];
            float gate = 1.0f / (1.0f + __expf(-x));
            atomicAdd(aggp + q, gate * vn[q]);
            lsum[q] += x;
            lsq[q]  += x * x;
        }
    }

    // block-level BN stat reduction: 16 (ty) partials per column
    __syncthreads();
#pragma unroll
    for (int q = 0; q < 8; q++) red[ty][j0 + q] = lsum[q];
    __syncthreads();
    if (tid < 128) {
        float s = 0.f;
#pragma unroll
        for (int t = 0; t < 16; t++) s += red[t][tid];
        atomicAdd(&g_stats[2 * H + tid], s);
    }
    __syncthreads();
#pragma unroll
    for (int q = 0; q < 8; q++) red[ty][j0 + q] = lsq[q];
    __syncthreads();
    if (tid < 128) {
        float s = 0.f;
#pragma unroll
        for (int t = 0; t < 16; t++) s += red[t][tid];
        atomicAdd(&g_stats[3 * H + tid], s);
    }
}

// ---------------------------------------------------------------------------
// k_nstats: column sums / sumsqs of agg (= Uh + scatter) for node BN
// ---------------------------------------------------------------------------
__global__ void k_nstats(int V) {
    int j = threadIdx.x & 127;
    int half = threadIdx.x >> 7;  // 0/1
    float s = 0.f, s2 = 0.f;
    for (int r = blockIdx.x * 2 + half; r < V; r += gridDim.x * 2) {
        float x = g_agg[(size_t)r * H + j];
        s += x; s2 += x * x;
    }
    __shared__ float shs[128], shq[128];
    if (half == 1) { shs[j] = s; shq[j] = s2; }
    __syncthreads();
    if (half == 0) {
        atomicAdd(&g_stats[j],     s  + shs[j]);
        atomicAdd(&g_stats[H + j], s2 + shq[j]);
    }
}

// ---------------------------------------------------------------------------
// k_finalize: turn sums into per-column (scale, shift) for both BNs
// ---------------------------------------------------------------------------
__global__ void k_finalize(const float* __restrict__ gh, const float* __restrict__ bh,
                           const float* __restrict__ ge, const float* __restrict__ be,
                           int V, int E) {
    int j = threadIdx.x;
    float invV = 1.0f / (float)V, invE = 1.0f / (float)E;
    float mh = g_stats[j] * invV;
    float vh = g_stats[H + j] * invV - mh * mh;
    float sc = gh[j] * rsqrtf(vh + 1e-5f);
    g_scale_h[j] = sc;
    g_shift_h[j] = bh[j] - mh * sc;
    float me = g_stats[2 * H + j] * invE;
    float ve = g_stats[3 * H + j] * invE - me * me;
    float se = ge[j] * rsqrtf(ve + 1e-5f);
    g_scale_e[j] = se;
    g_shift_e[j] = be[j] - me * se;
}

// ---------------------------------------------------------------------------
// k_nodeout: x_out = h + relu(BN(agg))
// ---------------------------------------------------------------------------
__global__ void k_nodeout(const float* __restrict__ h, float* __restrict__ out, int V) {
    int idx = blockIdx.x * blockDim.x + threadIdx.x;  // float4 index
    int total = V * (H / 4);
    if (idx >= total) return;
    int j = (idx & 31) * 4;
    float4 a  = *(const float4*)&g_agg[(size_t)idx * 4];
    float4 sc = *(const float4*)&g_scale_h[j];
    float4 sh = *(const float4*)&g_shift_h[j];
    float4 hv = *(const float4*)&h[(size_t)idx * 4];
    float4 r;
    r.x = hv.x + fmaxf(fmaf(a.x, sc.x, sh.x), 0.f);
    r.y = hv.y + fmaxf(fmaf(a.y, sc.y, sh.y), 0.f);
    r.z = hv.z + fmaxf(fmaf(a.z, sc.z, sh.z), 0.f);
    r.w = hv.w + fmaxf(fmaf(a.w, sc.w, sh.w), 0.f);
    *(float4*)&out[(size_t)idx * 4] = r;
}

// ---------------------------------------------------------------------------
// k_edgeout: e_out = e + relu(BN(e_pre))@Wo + cvec   (BN+relu fused in A-load)
// ---------------------------------------------------------------------------
__global__ __launch_bounds__(256) void k_edgeout(
        const float* __restrict__ e, const float* __restrict__ Wo,
        float* __restrict__ out, int E) {
    __shared__ float As[16][64];
    __shared__ float Bs[16][128];
    __shared__ float cvS[128];

    int tid = threadIdx.x;
    if (tid < 128) cvS[tid] = g_cvec[tid];

    int e0 = blockIdx.x * 64;
    int ty = tid >> 4, tx = tid & 15;
    ull acc[4][4] = {};

    for (int kk = 0; kk < H; kk += 16) {
        int m = tid >> 2, kq = (tid & 3) * 4;
        int row = e0 + m;
        float4 av = make_float4(0.f, 0.f, 0.f, 0.f);
        if (row < E) {
            av = *(const float4*)&g_epre[(size_t)row * H + kk + kq];
            float4 sc = *(const float4*)&g_scale_e[kk + kq];
            float4 sh = *(const float4*)&g_shift_e[kk + kq];
            av.x = fmaxf(fmaf(av.x, sc.x, sh.x), 0.f);
            av.y = fmaxf(fmaf(av.y, sc.y, sh.y), 0.f);
            av.z = fmaxf(fmaf(av.z, sc.z, sh.z), 0.f);
            av.w = fmaxf(fmaf(av.w, sc.w, sh.w), 0.f);
        }
        As[kq][m] = av.x; As[kq + 1][m] = av.y; As[kq + 2][m] = av.z; As[kq + 3][m] = av.w;
#pragma unroll
        for (int f = tid; f < 512; f += 256) {
            int k = f >> 5, j = (f & 31) * 4;
            *(float4*)&Bs[k][j] = *(const float4*)&Wo[(size_t)(kk + k) * H + j];
        }
        __syncthreads();
        mm_step(As, Bs, acc, ty, tx);
        __syncthreads();
    }

    int j0 = tx * 8;
#pragma unroll
    for (int i = 0; i < 4; i++) {
        int ei = e0 + ty * 4 + i;
        if (ei >= E) continue;
        float c8[8]; unpack_row(acc[i], c8);
        float4 e0v = *(const float4*)&e[(size_t)ei * H + j0];
        float4 e1v = *(const float4*)&e[(size_t)ei * H + j0 + 4];
        float4 o0 = make_float4(e0v.x + c8[0] + cvS[j0 + 0],
                                e0v.y + c8[1] + cvS[j0 + 1],
                                e0v.z + c8[2] + cvS[j0 + 2],
                                e0v.w + c8[3] + cvS[j0 + 3]);
        float4 o1 = make_float4(e1v.x + c8[4] + cvS[j0 + 4],
                                e1v.y + c8[5] + cvS[j0 + 5],
                                e1v.z + c8[6] + cvS[j0 + 6],
                                e1v.w + c8[7] + cvS[j0 + 7]);
        *(float4*)&out[(size_t)ei * H + j0]     = o0;
        *(float4*)&out[(size_t)ei * H + j0 + 4] = o1;
    }
}

// ---------------------------------------------------------------------------
extern "C" void kernel_launch(void* const* d_in, const int* in_sizes, int n_in,
                              void* d_out, int out_size) {
    const float* h        = (const float*)d_in[0];
    const float* e        = (const float*)d_in[1];
    const float* time_emb = (const float*)d_in[2];
    const int*   eidx     = (const int*)d_in[3];
    const float* WU = (const float*)d_in[4];  const float* bU = (const float*)d_in[5];
    const float* WV = (const float*)d_in[6];  const float* bV = (const float*)d_in[7];
    const float* WA = (const float*)d_in[8];  const float* bA = (const float*)d_in[9];
    const float* WB = (const float*)d_in[10]; const float* bB = (const float*)d_in[11];
    const float* WC = (const float*)d_in[12]; const float* bC = (const float*)d_in[13];
    const float* Wt = (const float*)d_in[14]; const float* bt = (const float*)d_in[15];
    const float* Wo = (const float*)d_in[16]; const float* bo = (const float*)d_in[17];
    const float* gh = (const float*)d_in[18]; const float* bh = (const float*)d_in[19];
    const float* ge = (const float*)d_in[20]; const float* be = (const float*)d_in[21];

    int V = in_sizes[0] / H;
    int E = in_sizes[3] / 2;

    float* xout = (float*)d_out;
    float* eout = xout + (size_t)V * H;

    k_init<<<1, 128>>>(time_emb, Wt, bt, Wo, bo);
    k_node<<<dim3((V + 63) / 64, 4), 256>>>(h, WU, bU, WV, bV, WA, bA, WB, bB, V);
    k_edge<<<(E + 63) / 64, 256>>>(e, WC, bC, eidx, E);
    k_nstats<<<200, 256>>>(V);
    k_finalize<<<1, 128>>>(gh, bh, ge, be, V, E);
    k_nodeout<<<(V * (H / 4) + 255) / 256, 256>>>(h, xout, V);
    k_edgeout<<<(E + 63) / 64, 256>>>(e, Wo, eout, E);
}

// round 4
// speedup vs baseline: 1.6011x; 1.6011x over previous
#include <cuda_runtime.h>
#include <cuda_bf16.h>
#include <cstdint>

// ---------------------------------------------------------------------------
// DAGCondGNNEncoder on GB300 (sm_103 base target -> HMMA mma.sync path).
//   Uh/Vn/Ah/Bh = h@W* + b*          (k_node, 4 GEMMs)
//   e_pre = (e@WC+bC) + Ah[col]+Bh[row]; agg[row] += sigmoid(e_pre)*Vn[col]
//   x_out = h + relu(BN(Uh+agg)); e_out = e + relu(BN(e_pre))@Wo + cvec
// GEMM: D = Ahi@Bhi + Ahi@Blo + Alo@Bhi (split-bf16, fp32 accum, mma.m16n8k16)
// ---------------------------------------------------------------------------

#define H 128
#define VMAX 50000
#define EMAX 625000

// ---- device scratch ----
__device__ __align__(16) float g_agg[(size_t)VMAX * H];
__device__ __align__(16) float g_Vn [(size_t)VMAX * H];
__device__ __align__(16) float g_Ah [(size_t)VMAX * H];
__device__ __align__(16) float g_Bh [(size_t)VMAX * H];
__device__ __align__(16) float g_epre[(size_t)EMAX * H];
__device__ __align__(16) float g_stats[4 * H];
__device__ __align__(16) float g_cvec[H];
__device__ __align__(16) float g_scale_h[H];
__device__ __align__(16) float g_shift_h[H];
__device__ __align__(16) float g_scale_e[H];
__device__ __align__(16) float g_shift_e[H];
// per-weight pre-swizzled bf16 images: [hi 32KB][lo 32KB], W^T layout [n][k]
__device__ __align__(16) unsigned char g_Bimg[6 * 65536];

// ---- smem layout (dynamic) ----
#define SM_IDX_R 64
#define SM_IDX_C 576
#define SM_A     4096              // A hi 32KB, A lo at +32768
#define SM_B     (4096 + 65536)    // B hi 32KB, B lo at +32768
#define SM_C     4096              // fp32 C tile overlays A after compute
#define CSTRIDE  132               // floats per C row (128 + 4 pad)
#define SM_SRED  71680
#define SM_QRED  75776
#define SMEM_BYTES (4096 + 131072)

// ---- helpers ----
__device__ __forceinline__ uint32_t smem_u32(const void* p) {
    uint32_t a;
    asm("{ .reg .u64 t; cvta.to.shared.u64 t, %1; cvt.u32.u64 %0, t; }" : "=r"(a) : "l"(p));
    return a;
}
__device__ __forceinline__ uint32_t bpack(float a, float b) {
    __nv_bfloat162 t = __floats2bfloat162_rn(a, b);
    return *reinterpret_cast<uint32_t*>(&t);
}
__device__ __forceinline__ float bres(float a) {
    __nv_bfloat16 hh = __float2bfloat16_rn(a);
    return a - __bfloat162float(hh);
}
// write 8 fp32 as bf16 hi(16B) + lo(16B) at swizzled offset
__device__ __forceinline__ void storeA8(char* hiP, char* loP, uint32_t off, const float* v) {
    uint4 hv, lv;
    hv.x = bpack(v[0], v[1]); hv.y = bpack(v[2], v[3]);
    hv.z = bpack(v[4], v[5]); hv.w = bpack(v[6], v[7]);
    lv.x = bpack(bres(v[0]), bres(v[1])); lv.y = bpack(bres(v[2]), bres(v[3]));
    lv.z = bpack(bres(v[4]), bres(v[5])); lv.w = bpack(bres(v[6]), bres(v[7]));
    *(uint4*)(hiP + off) = hv;
    *(uint4*)(loP + off) = lv;
}

__device__ __forceinline__ void ldsm4(uint32_t r[4], uint32_t addr) {
    asm volatile("ldmatrix.sync.aligned.m8n8.x4.shared.b16 {%0,%1,%2,%3}, [%4];"
        : "=r"(r[0]), "=r"(r[1]), "=r"(r[2]), "=r"(r[3]) : "r"(addr));
}
__device__ __forceinline__ void mma16816(float c[4], const uint32_t a[4], uint32_t b0, uint32_t b1) {
    asm volatile("mma.sync.aligned.m16n8k16.row.col.f32.bf16.bf16.f32 "
        "{%0,%1,%2,%3},{%4,%5,%6,%7},{%8,%9},{%0,%1,%2,%3};"
        : "+f"(c[0]), "+f"(c[1]), "+f"(c[2]), "+f"(c[3])
        : "r"(a[0]), "r"(a[1]), "r"(a[2]), "r"(a[3]), "r"(b0), "r"(b1));
}
__device__ __forceinline__ void redv2(float* p, float a, float b) {
    asm volatile("red.global.add.v2.f32 [%0], {%1, %2};" :: "l"(p), "f"(a), "f"(b) : "memory");
}

// ---- GEMM core: 128x128x128 tile, 8 warps, warp tile 32x64 ----
__device__ __forceinline__ void gemm_compute(uint32_t sAu, uint32_t sBu, float C[2][8][4]) {
    int tid = threadIdx.x, lane = tid & 31, wid = tid >> 5;
    int rm = (wid & 3) * 32, cn = (wid >> 2) * 64;
#pragma unroll
    for (int mf = 0; mf < 2; mf++)
#pragma unroll
        for (int nf = 0; nf < 8; nf++)
#pragma unroll
            for (int q = 0; q < 4; q++) C[mf][nf][q] = 0.f;

    int xr = lane & 7;
    int arow = xr + ((lane >> 3) & 1) * 8;
    int ahs = lane >> 4;
    int bhs = (lane >> 3) & 1;
    int bnr = xr + (lane >> 4) * 8;
    uint32_t aB0 = sAu + (uint32_t)(rm + arow) * 256;
    uint32_t aB1 = aB0 + 16 * 256;
    uint32_t bB[4];
#pragma unroll
    for (int g = 0; g < 4; g++) bB[g] = sBu + (uint32_t)(cn + g * 16 + bnr) * 256;

#pragma unroll
    for (int ks = 0; ks < 8; ks++) {
        uint32_t oA = (uint32_t)(((ks * 2 + ahs) ^ xr) << 4);
        uint32_t oB = (uint32_t)(((ks * 2 + bhs) ^ xr) << 4);
        uint32_t aH0[4], aH1[4], aL0[4], aL1[4];
        ldsm4(aH0, aB0 + oA);
        ldsm4(aH1, aB1 + oA);
        ldsm4(aL0, aB0 + 32768 + oA);
        ldsm4(aL1, aB1 + 32768 + oA);
        uint32_t bH[4][4], bL[4][4];
#pragma unroll
        for (int g = 0; g < 4; g++) {
            ldsm4(bH[g], bB[g] + oB);
            ldsm4(bL[g], bB[g] + 32768 + oB);
        }
#pragma unroll
        for (int g = 0; g < 4; g++) {
            mma16816(C[0][2*g],   aH0, bH[g][0], bH[g][1]);
            mma16816(C[0][2*g+1], aH0, bH[g][2], bH[g][3]);
            mma16816(C[1][2*g],   aH1, bH[g][0], bH[g][1]);
            mma16816(C[1][2*g+1], aH1, bH[g][2], bH[g][3]);
            mma16816(C[0][2*g],   aH0, bL[g][0], bL[g][1]);
            mma16816(C[0][2*g+1], aH0, bL[g][2], bL[g][3]);
            mma16816(C[1][2*g],   aH1, bL[g][0], bL[g][1]);
            mma16816(C[1][2*g+1], aH1, bL[g][2], bL[g][3]);
            mma16816(C[0][2*g],   aL0, bH[g][0], bH[g][1]);
            mma16816(C[0][2*g+1], aL0, bH[g][2], bH[g][3]);
            mma16816(C[1][2*g],   aL1, bH[g][0], bH[g][1]);
            mma16816(C[1][2*g+1], aL1, bH[g][2], bH[g][3]);
        }
    }
}

__device__ __forceinline__ void gemm_storeC(float* Cs, float C[2][8][4]) {
    int tid = threadIdx.x, lane = tid & 31, wid = tid >> 5;
    int rm = (wid & 3) * 32, cn = (wid >> 2) * 64;
    int r = lane >> 2, c2 = 2 * (lane & 3);
#pragma unroll
    for (int mf = 0; mf < 2; mf++)
#pragma unroll
        for (int nf = 0; nf < 8; nf++) {
            int row = rm + mf * 16 + r;
            int col = cn + nf * 8 + c2;
            *(float2*)(Cs + row * CSTRIDE + col)       = make_float2(C[mf][nf][0], C[mf][nf][1]);
            *(float2*)(Cs + (row + 8) * CSTRIDE + col) = make_float2(C[mf][nf][2], C[mf][nf][3]);
        }
}

// ---- tile loaders ----
__device__ __forceinline__ void load_A_f32(const float* src, int nrows, char* sA) {
    int tid = threadIdx.x;
#pragma unroll
    for (int it = 0; it < 8; it++) {
        int s = it * 256 + tid;
        int row = s >> 4, kseg = s & 15;
        float v[8] = {0.f, 0.f, 0.f, 0.f, 0.f, 0.f, 0.f, 0.f};
        if (row < nrows) {
            float4 f0 = *(const float4*)(src + (size_t)row * H + kseg * 8);
            float4 f1 = *(const float4*)(src + (size_t)row * H + kseg * 8 + 4);
            v[0] = f0.x; v[1] = f0.y; v[2] = f0.z; v[3] = f0.w;
            v[4] = f1.x; v[5] = f1.y; v[6] = f1.z; v[7] = f1.w;
        }
        uint32_t off = (uint32_t)row * 256 + (uint32_t)((kseg ^ (row & 7)) << 4);
        storeA8(sA, sA + 32768, off, v);
    }
}

__device__ __forceinline__ void load_A_bn(const float* src, int nrows, char* sA) {
    int tid = threadIdx.x;
#pragma unroll
    for (int it = 0; it < 8; it++) {
        int s = it * 256 + tid;
        int row = s >> 4, kseg = s & 15;
        float v[8] = {0.f, 0.f, 0.f, 0.f, 0.f, 0.f, 0.f, 0.f};
        if (row < nrows) {
            float4 f0 = *(const float4*)(src + (size_t)row * H + kseg * 8);
            float4 f1 = *(const float4*)(src + (size_t)row * H + kseg * 8 + 4);
            float4 s0 = *(const float4*)(g_scale_e + kseg * 8);
            float4 s1 = *(const float4*)(g_scale_e + kseg * 8 + 4);
            float4 t0 = *(const float4*)(g_shift_e + kseg * 8);
            float4 t1 = *(const float4*)(g_shift_e + kseg * 8 + 4);
            v[0] = fmaxf(fmaf(f0.x, s0.x, t0.x), 0.f);
            v[1] = fmaxf(fmaf(f0.y, s0.y, t0.y), 0.f);
            v[2] = fmaxf(fmaf(f0.z, s0.z, t0.z), 0.f);
            v[3] = fmaxf(fmaf(f0.w, s0.w, t0.w), 0.f);
            v[4] = fmaxf(fmaf(f1.x, s1.x, t1.x), 0.f);
            v[5] = fmaxf(fmaf(f1.y, s1.y, t1.y), 0.f);
            v[6] = fmaxf(fmaf(f1.z, s1.z, t1.z), 0.f);
            v[7] = fmaxf(fmaf(f1.w, s1.w, t1.w), 0.f);
        }
        uint32_t off = (uint32_t)row * 256 + (uint32_t)((kseg ^ (row & 7)) << 4);
        storeA8(sA, sA + 32768, off, v);
    }
}

__device__ __forceinline__ void copy_B(int widx, char* sB) {
    const uint4* g = (const uint4*)(g_Bimg + (size_t)widx * 65536);
    uint4* d = (uint4*)sB;
    int tid = threadIdx.x;
#pragma unroll
    for (int it = 0; it < 16; it++) d[it * 256 + tid] = g[it * 256 + tid];
}

// ---------------------------------------------------------------------------
// k_init: zero BN accumulators; cvec = (time@Wt+bt)@Wo + bo
// ---------------------------------------------------------------------------
__global__ void k_init(const float* __restrict__ time_emb,
                       const float* __restrict__ Wt, const float* __restrict__ bt,
                       const float* __restrict__ Wo, const float* __restrict__ bo) {
    int j = threadIdx.x;  // 128
    for (int i = j; i < 4 * H; i += H) g_stats[i] = 0.0f;
    __shared__ float tv[H];
    float acc = bt[j];
    for (int k = 0; k < H; k++) acc += time_emb[k] * Wt[k * H + j];
    tv[j] = acc;
    __syncthreads();
    float c = bo[j];
    for (int k = 0; k < H; k++) c += tv[k] * Wo[k * H + j];
    g_cvec[j] = c;
}

// ---------------------------------------------------------------------------
// k_prep: W[k][n] -> transposed, split, swizzled bf16 images [n][k] hi/lo
// ---------------------------------------------------------------------------
__global__ void k_prep(const float* __restrict__ WU, const float* __restrict__ WV,
                       const float* __restrict__ WA, const float* __restrict__ WB,
                       const float* __restrict__ WC, const float* __restrict__ Wo) {
    const float* Ws[6] = {WU, WV, WA, WB, WC, Wo};
    const float* W = Ws[blockIdx.x];
    unsigned char* img = g_Bimg + (size_t)blockIdx.x * 65536;
    int tid = threadIdx.x;
    for (int it = 0; it < 64; it++) {
        int idx = it * 256 + tid;
        int k = idx >> 7, n = idx & 127;
        float v = W[k * H + n];
        __nv_bfloat16 hi = __float2bfloat16_rn(v);
        __nv_bfloat16 lo = __float2bfloat16_rn(v - __bfloat162float(hi));
        uint32_t off = (uint32_t)n * 256 + (uint32_t)((((k >> 3) ^ (n & 7))) << 4) + (k & 7) * 2;
        *(__nv_bfloat16*)(img + off) = hi;
        *(__nv_bfloat16*)(img + 32768 + off) = lo;
    }
}

// ---------------------------------------------------------------------------
// k_node: 128-row h tile @ {WU,WV,WA,WB} -> {agg,Vn,Ah,Bh} (+bias)
// ---------------------------------------------------------------------------
__global__ __launch_bounds__(256, 1) void k_node(
        const float* __restrict__ h,
        const float* __restrict__ bU, const float* __restrict__ bV,
        const float* __restrict__ bA, const float* __restrict__ bB, int V) {
    extern __shared__ char sm[];
    uint32_t sb = smem_u32(sm);
    int tid = threadIdx.x;
    int widx = blockIdx.y;
    int r0 = blockIdx.x * 128;
    int nrows = V - r0; if (nrows > 128) nrows = 128;

    copy_B(widx, sm + SM_B);
    load_A_f32(h + (size_t)r0 * H, nrows, sm + SM_A);
    __syncthreads();

    float C[2][8][4];
    gemm_compute(sb + SM_A, sb + SM_B, C);
    __syncthreads();
    gemm_storeC((float*)(sm + SM_C), C);
    __syncthreads();

    float* out; const float* bias;
    switch (widx) {
        case 0:  out = g_agg; bias = bU; break;
        case 1:  out = g_Vn;  bias = bV; break;
        case 2:  out = g_Ah;  bias = bA; break;
        default: out = g_Bh;  bias = bB; break;
    }
    const float* Cs = (const float*)(sm + SM_C);
#pragma unroll
    for (int it = 0; it < 16; it++) {
        int idx = it * 256 + tid;
        int row = idx >> 5, cs = idx & 31;
        if (r0 + row < V) {
            float4 c = *(const float4*)(Cs + row * CSTRIDE + cs * 4);
            float4 b = *(const float4*)(bias + cs * 4);
            c.x += b.x; c.y += b.y; c.z += b.z; c.w += b.w;
            *(float4*)(out + (size_t)(r0 + row) * H + cs * 4) = c;
        }
    }
}

// ---------------------------------------------------------------------------
// k_edge: Ce GEMM + gathers + e_pre store + gated scatter + inline BN stats
// ---------------------------------------------------------------------------
__global__ __launch_bounds__(256, 1) void k_edge(
        const float* __restrict__ e, const float* __restrict__ bC,
        const int* __restrict__ eidx, int E) {
    extern __shared__ char sm[];
    uint32_t sb = smem_u32(sm);
    int tid = threadIdx.x;
    int e0 = blockIdx.x * 128;
    int nrows = E - e0; if (nrows > 128) nrows = 128;

    int* rI = (int*)(sm + SM_IDX_R);
    int* cI = (int*)(sm + SM_IDX_C);
    if (tid < 128) {
        int ei = e0 + tid;
        rI[tid] = (ei < E) ? eidx[ei] : 0;
    } else {
        int t = tid - 128, ei = e0 + t;
        cI[t] = (ei < E) ? eidx[(size_t)E + ei] : 0;
    }

    copy_B(4, sm + SM_B);
    load_A_f32(e + (size_t)e0 * H, nrows, sm + SM_A);
    __syncthreads();

    float C[2][8][4];
    gemm_compute(sb + SM_A, sb + SM_B, C);
    __syncthreads();
    gemm_storeC((float*)(sm + SM_C), C);
    __syncthreads();

    int lane = tid & 31, w = tid >> 5;
    const float* Cs = (const float*)(sm + SM_C);
    float4 bc = *(const float4*)(bC + lane * 4);
    float s0 = 0.f, s1 = 0.f, s2 = 0.f, s3 = 0.f;
    float q0 = 0.f, q1 = 0.f, q2 = 0.f, q3 = 0.f;
#pragma unroll
    for (int k = 0; k < 16; k++) {
        int m = w + k * 8;
        int ei = e0 + m;
        if (ei < E) {
            int rv = rI[m], cv = cI[m];
            float4 cc = *(const float4*)(Cs + m * CSTRIDE + lane * 4);
            float4 ah = *(const float4*)(g_Ah + (size_t)cv * H + lane * 4);
            float4 bh = *(const float4*)(g_Bh + (size_t)rv * H + lane * 4);
            float4 vn = *(const float4*)(g_Vn + (size_t)cv * H + lane * 4);
            float4 x;
            x.x = cc.x + bc.x + ah.x + bh.x;
            x.y = cc.y + bc.y + ah.y + bh.y;
            x.z = cc.z + bc.z + ah.z + bh.z;
            x.w = cc.w + bc.w + ah.w + bh.w;
            *(float4*)(g_epre + (size_t)ei * H + lane * 4) = x;
            float ga = vn.x / (1.f + __expf(-x.x));
            float gb = vn.y / (1.f + __expf(-x.y));
            float gc = vn.z / (1.f + __expf(-x.z));
            float gd = vn.w / (1.f + __expf(-x.w));
            float* agp = g_agg + (size_t)rv * H + lane * 4;
            redv2(agp, ga, gb);
            redv2(agp + 2, gc, gd);
            s0 += x.x; s1 += x.y; s2 += x.z; s3 += x.w;
            q0 += x.x * x.x; q1 += x.y * x.y; q2 += x.z * x.z; q3 += x.w * x.w;
        }
    }
    float* sr = (float*)(sm + SM_SRED);
    float* qr = (float*)(sm + SM_QRED);
    *(float4*)(sr + w * 128 + lane * 4) = make_float4(s0, s1, s2, s3);
    *(float4*)(qr + w * 128 + lane * 4) = make_float4(q0, q1, q2, q3);
    __syncthreads();
    if (tid < 128) {
        float a = 0.f, b = 0.f;
#pragma unroll
        for (int ww = 0; ww < 8; ww++) { a += sr[ww * 128 + tid]; b += qr[ww * 128 + tid]; }
        atomicAdd(&g_stats[2 * H + tid], a);
        atomicAdd(&g_stats[3 * H + tid], b);
    }
}

// ---------------------------------------------------------------------------
// k_edgeout: A = relu(BN(e_pre)) on load; @Wo; out = e + C + cvec
// ---------------------------------------------------------------------------
__global__ __launch_bounds__(256, 1) void k_edgeout(
        const float* __restrict__ e, float* __restrict__ out, int E) {
    extern __shared__ char sm[];
    uint32_t sb = smem_u32(sm);
    int tid = threadIdx.x;
    int e0 = blockIdx.x * 128;
    int nrows = E - e0; if (nrows > 128) nrows = 128;

    copy_B(5, sm + SM_B);
    load_A_bn(g_epre + (size_t)e0 * H, nrows, sm + SM_A);
    __syncthreads();

    float C[2][8][4];
    gemm_compute(sb + SM_A, sb + SM_B, C);
    __syncthreads();
    gemm_storeC((float*)(sm + SM_C), C);
    __syncthreads();

    int lane = tid & 31, w = tid >> 5;
    const float* Cs = (const float*)(sm + SM_C);
    float4 cv4 = *(const float4*)(g_cvec + lane * 4);
#pragma unroll
    for (int k = 0; k < 16; k++) {
        int m = w + k * 8;
        int ei = e0 + m;
        if (ei < E) {
            float4 cc = *(const float4*)(Cs + m * CSTRIDE + lane * 4);
            float4 ev = *(const float4*)(e + (size_t)ei * H + lane * 4);
            float4 o;
            o.x = ev.x + cc.x + cv4.x;
            o.y = ev.y + cc.y + cv4.y;
            o.z = ev.z + cc.z + cv4.z;
            o.w = ev.w + cc.w + cv4.w;
            *(float4*)(out + (size_t)ei * H + lane * 4) = o;
        }
    }
}

// ---------------------------------------------------------------------------
// k_nstats: per-column sum/sumsq of agg (node BN)
// ---------------------------------------------------------------------------
__global__ void k_nstats(int rows) {
    int tid = threadIdx.x;
    int cg = tid & 31, wr = tid >> 5;
    float4 s = make_float4(0.f, 0.f, 0.f, 0.f);
    float4 qq = make_float4(0.f, 0.f, 0.f, 0.f);
    const float4* s4 = (const float4*)g_agg;
    for (int r = blockIdx.x * 8 + wr; r < rows; r += gridDim.x * 8) {
        float4 x = s4[(size_t)r * 32 + cg];
        s.x += x.x; s.y += x.y; s.z += x.z; s.w += x.w;
        qq.x += x.x * x.x; qq.y += x.y * x.y; qq.z += x.z * x.z; qq.w += x.w * x.w;
    }
    __shared__ float sh1[8][128], sh2[8][128];
    *(float4*)&sh1[wr][cg * 4] = s;
    *(float4*)&sh2[wr][cg * 4] = qq;
    __syncthreads();
    if (tid < 128) {
        float a = 0.f, b = 0.f;
#pragma unroll
        for (int ww = 0; ww < 8; ww++) { a += sh1[ww][tid]; b += sh2[ww][tid]; }
        atomicAdd(&g_stats[tid], a);
        atomicAdd(&g_stats[H + tid], b);
    }
}

// ---------------------------------------------------------------------------
__global__ void k_finalize(const float* __restrict__ gh, const float* __restrict__ bh,
                           const float* __restrict__ ge, const float* __restrict__ be,
                           int V, int E) {
    int j = threadIdx.x;
    float invV = 1.0f / (float)V, invE = 1.0f / (float)E;
    float mh = g_stats[j] * invV;
    float vh = g_stats[H + j] * invV - mh * mh;
    float sc = gh[j] * rsqrtf(vh + 1e-5f);
    g_scale_h[j] = sc;
    g_shift_h[j] = bh[j] - mh * sc;
    float me = g_stats[2 * H + j] * invE;
    float ve = g_stats[3 * H + j] * invE - me * me;
    float se = ge[j] * rsqrtf(ve + 1e-5f);
    g_scale_e[j] = se;
    g_shift_e[j] = be[j] - me * se;
}

// ---------------------------------------------------------------------------
__global__ void k_nodeout(const float* __restrict__ h, float* __restrict__ out, int V) {
    int idx = blockIdx.x * blockDim.x + threadIdx.x;
    int total = V * (H / 4);
    if (idx >= total) return;
    int j = (idx & 31) * 4;
    float4 a  = *(const float4*)&g_agg[(size_t)idx * 4];
    float4 sc = *(const float4*)&g_scale_h[j];
    float4 sh = *(const float4*)&g_shift_h[j];
    float4 hv = *(const float4*)&h[(size_t)idx * 4];
    float4 r;
    r.x = hv.x + fmaxf(fmaf(a.x, sc.x, sh.x), 0.f);
    r.y = hv.y + fmaxf(fmaf(a.y, sc.y, sh.y), 0.f);
    r.z = hv.z + fmaxf(fmaf(a.z, sc.z, sh.z), 0.f);
    r.w = hv.w + fmaxf(fmaf(a.w, sc.w, sh.w), 0.f);
    *(float4*)&out[(size_t)idx * 4] = r;
}

// ---------------------------------------------------------------------------
extern "C" void kernel_launch(void* const* d_in, const int* in_sizes, int n_in,
                              void* d_out, int out_size) {
    const float* h        = (const float*)d_in[0];
    const float* e        = (const float*)d_in[1];
    const float* time_emb = (const float*)d_in[2];
    const int*   eidx     = (const int*)d_in[3];
    const float* WU = (const float*)d_in[4];  const float* bU = (const float*)d_in[5];
    const float* WV = (const float*)d_in[6];  const float* bV = (const float*)d_in[7];
    const float* WA = (const float*)d_in[8];  const float* bA = (const float*)d_in[9];
    const float* WB = (const float*)d_in[10]; const float* bB = (const float*)d_in[11];
    const float* WC = (const float*)d_in[12]; const float* bC = (const float*)d_in[13];
    const float* Wt = (const float*)d_in[14]; const float* bt = (const float*)d_in[15];
    const float* Wo = (const float*)d_in[16]; const float* bo = (const float*)d_in[17];
    const float* gh = (const float*)d_in[18]; const float* bh = (const float*)d_in[19];
    const float* ge = (const float*)d_in[20]; const float* be = (const float*)d_in[21];

    int V = in_sizes[0] / H;
    int E = in_sizes[3] / 2;

    float* xout = (float*)d_out;
    float* eout = xout + (size_t)V * H;

    cudaFuncSetAttribute(k_node,    cudaFuncAttributeMaxDynamicSharedMemorySize, SMEM_BYTES);
    cudaFuncSetAttribute(k_edge,    cudaFuncAttributeMaxDynamicSharedMemorySize, SMEM_BYTES);
    cudaFuncSetAttribute(k_edgeout, cudaFuncAttributeMaxDynamicSharedMemorySize, SMEM_BYTES);

    int vTiles = (V + 127) / 128;
    int eTiles = (E + 127) / 128;

    k_init<<<1, 128>>>(time_emb, Wt, bt, Wo, bo);
    k_prep<<<6, 256>>>(WU, WV, WA, WB, WC, Wo);
    k_node<<<dim3(vTiles, 4), 256, SMEM_BYTES>>>(h, bU, bV, bA, bB, V);
    k_edge<<<eTiles, 256, SMEM_BYTES>>>(e, bC, eidx, E);
    k_nstats<<<512, 256>>>(V);
    k_finalize<<<1, 128>>>(gh, bh, ge, be, V, E);
    k_nodeout<<<(V * (H / 4) + 255) / 256, 256>>>(h, xout, V);
    k_edgeout<<<eTiles, 256, SMEM_BYTES>>>(e, eout, E);
}

// round 5
// speedup vs baseline: 2.0828x; 1.3008x over previous
#include <cuda_runtime.h>
#include <cuda_bf16.h>
#include <cstdint>

// ---------------------------------------------------------------------------
// DAGCondGNNEncoder (sm_103 HMMA path): split-bf16 mma.sync GEMMs.
//   R5: 512-thread GEMM blocks (16 warps, warp tile 16x64) + L2 prefetch of
//   gather rows before the MMA phase in k_edge.
// ---------------------------------------------------------------------------

#define H 128
#define VMAX 50000
#define EMAX 625000

// ---- device scratch ----
__device__ __align__(16) float g_agg[(size_t)VMAX * H];
__device__ __align__(16) float g_Vn [(size_t)VMAX * H];
__device__ __align__(16) float g_Ah [(size_t)VMAX * H];
__device__ __align__(16) float g_Bh [(size_t)VMAX * H];
__device__ __align__(16) float g_epre[(size_t)EMAX * H];
__device__ __align__(16) float g_stats[4 * H];
__device__ __align__(16) float g_cvec[H];
__device__ __align__(16) float g_scale_h[H];
__device__ __align__(16) float g_shift_h[H];
__device__ __align__(16) float g_scale_e[H];
__device__ __align__(16) float g_shift_e[H];
// per-weight pre-swizzled bf16 images: [hi 32KB][lo 32KB], W^T layout [n][k]
__device__ __align__(16) unsigned char g_Bimg[6 * 65536];

// ---- smem layout (dynamic) ----
#define SM_IDX_R 64
#define SM_IDX_C 576
#define SM_A     4096              // A hi 32KB, A lo at +32768
#define SM_B     (4096 + 65536)    // B hi 32KB, B lo at +32768
#define SM_C     4096              // fp32 C tile overlays A (and 2KB of dead B)
#define CSTRIDE  132
#define SM_SRED  71680             // 16 warps x 128 floats (dead-B region)
#define SM_QRED  79872
#define SMEM_BYTES (4096 + 131072)

#define NT 512                     // threads per GEMM block

// ---- helpers ----
__device__ __forceinline__ uint32_t smem_u32(const void* p) {
    uint32_t a;
    asm("{ .reg .u64 t; cvta.to.shared.u64 t, %1; cvt.u32.u64 %0, t; }" : "=r"(a) : "l"(p));
    return a;
}
__device__ __forceinline__ uint32_t bpack(float a, float b) {
    __nv_bfloat162 t = __floats2bfloat162_rn(a, b);
    return *reinterpret_cast<uint32_t*>(&t);
}
__device__ __forceinline__ float bres(float a) {
    __nv_bfloat16 hh = __float2bfloat16_rn(a);
    return a - __bfloat162float(hh);
}
__device__ __forceinline__ void storeA8(char* hiP, char* loP, uint32_t off, const float* v) {
    uint4 hv, lv;
    hv.x = bpack(v[0], v[1]); hv.y = bpack(v[2], v[3]);
    hv.z = bpack(v[4], v[5]); hv.w = bpack(v[6], v[7]);
    lv.x = bpack(bres(v[0]), bres(v[1])); lv.y = bpack(bres(v[2]), bres(v[3]));
    lv.z = bpack(bres(v[4]), bres(v[5])); lv.w = bpack(bres(v[6]), bres(v[7]));
    *(uint4*)(hiP + off) = hv;
    *(uint4*)(loP + off) = lv;
}
__device__ __forceinline__ void ldsm4(uint32_t r[4], uint32_t addr) {
    asm volatile("ldmatrix.sync.aligned.m8n8.x4.shared.b16 {%0,%1,%2,%3}, [%4];"
        : "=r"(r[0]), "=r"(r[1]), "=r"(r[2]), "=r"(r[3]) : "r"(addr));
}
__device__ __forceinline__ void mma16816(float c[4], const uint32_t a[4], uint32_t b0, uint32_t b1) {
    asm volatile("mma.sync.aligned.m16n8k16.row.col.f32.bf16.bf16.f32 "
        "{%0,%1,%2,%3},{%4,%5,%6,%7},{%8,%9},{%0,%1,%2,%3};"
        : "+f"(c[0]), "+f"(c[1]), "+f"(c[2]), "+f"(c[3])
        : "r"(a[0]), "r"(a[1]), "r"(a[2]), "r"(a[3]), "r"(b0), "r"(b1));
}
__device__ __forceinline__ void redv2(float* p, float a, float b) {
    asm volatile("red.global.add.v2.f32 [%0], {%1, %2};" :: "l"(p), "f"(a), "f"(b) : "memory");
}
__device__ __forceinline__ void pf_l2(const void* p) {
    asm volatile("prefetch.global.L2 [%0];" :: "l"(p));
}

// ---- GEMM core: 128x128x128 tile, 16 warps, warp tile 16x64 ----
__device__ __forceinline__ void gemm_compute(uint32_t sAu, uint32_t sBu, float C[8][4]) {
    int tid = threadIdx.x, lane = tid & 31, wid = tid >> 5;
    int rm = (wid & 7) * 16, cn = (wid >> 3) * 64;
#pragma unroll
    for (int nf = 0; nf < 8; nf++)
#pragma unroll
        for (int q = 0; q < 4; q++) C[nf][q] = 0.f;

    int xr = lane & 7;
    int arow = xr + ((lane >> 3) & 1) * 8;
    int ahs = lane >> 4;
    int bhs = (lane >> 3) & 1;
    int bnr = xr + (lane >> 4) * 8;
    uint32_t aB = sAu + (uint32_t)(rm + arow) * 256;
    uint32_t bB[4];
#pragma unroll
    for (int g = 0; g < 4; g++) bB[g] = sBu + (uint32_t)(cn + g * 16 + bnr) * 256;

#pragma unroll
    for (int ks = 0; ks < 8; ks++) {
        uint32_t oA = (uint32_t)(((ks * 2 + ahs) ^ xr) << 4);
        uint32_t oB = (uint32_t)(((ks * 2 + bhs) ^ xr) << 4);
        uint32_t aH[4], aL[4];
        ldsm4(aH, aB + oA);
        ldsm4(aL, aB + 32768 + oA);
        uint32_t bH[4][4], bL[4][4];
#pragma unroll
        for (int g = 0; g < 4; g++) {
            ldsm4(bH[g], bB[g] + oB);
            ldsm4(bL[g], bB[g] + 32768 + oB);
        }
#pragma unroll
        for (int g = 0; g < 4; g++) {
            mma16816(C[2*g],   aH, bH[g][0], bH[g][1]);
            mma16816(C[2*g+1], aH, bH[g][2], bH[g][3]);
            mma16816(C[2*g],   aH, bL[g][0], bL[g][1]);
            mma16816(C[2*g+1], aH, bL[g][2], bL[g][3]);
            mma16816(C[2*g],   aL, bH[g][0], bH[g][1]);
            mma16816(C[2*g+1], aL, bH[g][2], bH[g][3]);
        }
    }
}

__device__ __forceinline__ void gemm_storeC(float* Cs, float C[8][4]) {
    int tid = threadIdx.x, lane = tid & 31, wid = tid >> 5;
    int rm = (wid & 7) * 16, cn = (wid >> 3) * 64;
    int r = lane >> 2, c2 = 2 * (lane & 3);
#pragma unroll
    for (int nf = 0; nf < 8; nf++) {
        int col = cn + nf * 8 + c2;
        *(float2*)(Cs + (rm + r) * CSTRIDE + col)     = make_float2(C[nf][0], C[nf][1]);
        *(float2*)(Cs + (rm + r + 8) * CSTRIDE + col) = make_float2(C[nf][2], C[nf][3]);
    }
}

// ---- tile loaders (512 threads) ----
__device__ __forceinline__ void load_A_f32(const float* src, int nrows, char* sA) {
    int tid = threadIdx.x;
#pragma unroll
    for (int it = 0; it < 4; it++) {
        int s = it * NT + tid;
        int row = s >> 4, kseg = s & 15;
        float v[8] = {0.f, 0.f, 0.f, 0.f, 0.f, 0.f, 0.f, 0.f};
        if (row < nrows) {
            float4 f0 = *(const float4*)(src + (size_t)row * H + kseg * 8);
            float4 f1 = *(const float4*)(src + (size_t)row * H + kseg * 8 + 4);
            v[0] = f0.x; v[1] = f0.y; v[2] = f0.z; v[3] = f0.w;
            v[4] = f1.x; v[5] = f1.y; v[6] = f1.z; v[7] = f1.w;
        }
        uint32_t off = (uint32_t)row * 256 + (uint32_t)((kseg ^ (row & 7)) << 4);
        storeA8(sA, sA + 32768, off, v);
    }
}

__device__ __forceinline__ void load_A_bn(const float* src, int nrows, char* sA) {
    int tid = threadIdx.x;
#pragma unroll
    for (int it = 0; it < 4; it++) {
        int s = it * NT + tid;
        int row = s >> 4, kseg = s & 15;
        float v[8] = {0.f, 0.f, 0.f, 0.f, 0.f, 0.f, 0.f, 0.f};
        if (row < nrows) {
            float4 f0 = *(const float4*)(src + (size_t)row * H + kseg * 8);
            float4 f1 = *(const float4*)(src + (size_t)row * H + kseg * 8 + 4);
            float4 s0 = *(const float4*)(g_scale_e + kseg * 8);
            float4 s1 = *(const float4*)(g_scale_e + kseg * 8 + 4);
            float4 t0 = *(const float4*)(g_shift_e + kseg * 8);
            float4 t1 = *(const float4*)(g_shift_e + kseg * 8 + 4);
            v[0] = fmaxf(fmaf(f0.x, s0.x, t0.x), 0.f);
            v[1] = fmaxf(fmaf(f0.y, s0.y, t0.y), 0.f);
            v[2] = fmaxf(fmaf(f0.z, s0.z, t0.z), 0.f);
            v[3] = fmaxf(fmaf(f0.w, s0.w, t0.w), 0.f);
            v[4] = fmaxf(fmaf(f1.x, s1.x, t1.x), 0.f);
            v[5] = fmaxf(fmaf(f1.y, s1.y, t1.y), 0.f);
            v[6] = fmaxf(fmaf(f1.z, s1.z, t1.z), 0.f);
            v[7] = fmaxf(fmaf(f1.w, s1.w, t1.w), 0.f);
        }
        uint32_t off = (uint32_t)row * 256 + (uint32_t)((kseg ^ (row & 7)) << 4);
        storeA8(sA, sA + 32768, off, v);
    }
}

__device__ __forceinline__ void copy_B(int widx, char* sB) {
    const uint4* g = (const uint4*)(g_Bimg + (size_t)widx * 65536);
    uint4* d = (uint4*)sB;
    int tid = threadIdx.x;
#pragma unroll
    for (int it = 0; it < 8; it++) d[it * NT + tid] = g[it * NT + tid];
}

// ---------------------------------------------------------------------------
__global__ void k_init(const float* __restrict__ time_emb,
                       const float* __restrict__ Wt, const float* __restrict__ bt,
                       const float* __restrict__ Wo, const float* __restrict__ bo) {
    int j = threadIdx.x;
    for (int i = j; i < 4 * H; i += H) g_stats[i] = 0.0f;
    __shared__ float tv[H];
    float acc = bt[j];
    for (int k = 0; k < H; k++) acc += time_emb[k] * Wt[k * H + j];
    tv[j] = acc;
    __syncthreads();
    float c = bo[j];
    for (int k = 0; k < H; k++) c += tv[k] * Wo[k * H + j];
    g_cvec[j] = c;
}

// ---------------------------------------------------------------------------
__global__ void k_prep(const float* __restrict__ WU, const float* __restrict__ WV,
                       const float* __restrict__ WA, const float* __restrict__ WB,
                       const float* __restrict__ WC, const float* __restrict__ Wo) {
    const float* Ws[6] = {WU, WV, WA, WB, WC, Wo};
    const float* W = Ws[blockIdx.x];
    unsigned char* img = g_Bimg + (size_t)blockIdx.x * 65536;
    int tid = threadIdx.x;
    for (int it = 0; it < 64; it++) {
        int idx = it * 256 + tid;
        int k = idx >> 7, n = idx & 127;
        float v = W[k * H + n];
        __nv_bfloat16 hi = __float2bfloat16_rn(v);
        __nv_bfloat16 lo = __float2bfloat16_rn(v - __bfloat162float(hi));
        uint32_t off = (uint32_t)n * 256 + (uint32_t)((((k >> 3) ^ (n & 7))) << 4) + (k & 7) * 2;
        *(__nv_bfloat16*)(img + off) = hi;
        *(__nv_bfloat16*)(img + 32768 + off) = lo;
    }
}

// ---------------------------------------------------------------------------
__global__ __launch_bounds__(NT, 1) void k_node(
        const float* __restrict__ h,
        const float* __restrict__ bU, const float* __restrict__ bV,
        const float* __restrict__ bA, const float* __restrict__ bB, int V) {
    extern __shared__ char sm[];
    uint32_t sb = smem_u32(sm);
    int tid = threadIdx.x;
    int widx = blockIdx.y;
    int r0 = blockIdx.x * 128;
    int nrows = V - r0; if (nrows > 128) nrows = 128;

    copy_B(widx, sm + SM_B);
    load_A_f32(h + (size_t)r0 * H, nrows, sm + SM_A);
    __syncthreads();

    float C[8][4];
    gemm_compute(sb + SM_A, sb + SM_B, C);
    __syncthreads();
    gemm_storeC((float*)(sm + SM_C), C);
    __syncthreads();

    float* out; const float* bias;
    switch (widx) {
        case 0:  out = g_agg; bias = bU; break;
        case 1:  out = g_Vn;  bias = bV; break;
        case 2:  out = g_Ah;  bias = bA; break;
        default: out = g_Bh;  bias = bB; break;
    }
    const float* Cs = (const float*)(sm + SM_C);
#pragma unroll
    for (int it = 0; it < 8; it++) {
        int idx = it * NT + tid;
        int row = idx >> 5, cs = idx & 31;
        if (r0 + row < V) {
            float4 c = *(const float4*)(Cs + row * CSTRIDE + cs * 4);
            float4 b = *(const float4*)(bias + cs * 4);
            c.x += b.x; c.y += b.y; c.z += b.z; c.w += b.w;
            *(float4*)(out + (size_t)(r0 + row) * H + cs * 4) = c;
        }
    }
}

// ---------------------------------------------------------------------------
__global__ __launch_bounds__(NT, 1) void k_edge(
        const float* __restrict__ e, const float* __restrict__ bC,
        const int* __restrict__ eidx, int E) {
    extern __shared__ char sm[];
    uint32_t sb = smem_u32(sm);
    int tid = threadIdx.x;
    int e0 = blockIdx.x * 128;
    int nrows = E - e0; if (nrows > 128) nrows = 128;

    int* rI = (int*)(sm + SM_IDX_R);
    int* cI = (int*)(sm + SM_IDX_C);
    if (tid < 128) {
        int ei = e0 + tid;
        rI[tid] = (ei < E) ? eidx[ei] : 0;
    } else if (tid < 256) {
        int t = tid - 128, ei = e0 + t;
        cI[t] = (ei < E) ? eidx[(size_t)E + ei] : 0;
    }

    copy_B(4, sm + SM_B);
    load_A_f32(e + (size_t)e0 * H, nrows, sm + SM_A);
    __syncthreads();

    // L2-prefetch all gather rows for this tile: 128 edges x {Ah[c],Bh[r],Vn[c]}
    // x 4 cache lines; latency overlaps the MMA phase below.
#pragma unroll
    for (int i = tid; i < 1536; i += NT) {
        int m = i & 127, sel = i >> 7;         // sel 0..11
        int arr = sel >> 2, part = (sel & 3) * 32;
        const float* p;
        if (arr == 0)      p = g_Ah + (size_t)cI[m] * H + part;
        else if (arr == 1) p = g_Bh + (size_t)rI[m] * H + part;
        else               p = g_Vn + (size_t)cI[m] * H + part;
        pf_l2(p);
    }

    float C[8][4];
    gemm_compute(sb + SM_A, sb + SM_B, C);
    __syncthreads();
    gemm_storeC((float*)(sm + SM_C), C);
    __syncthreads();

    int lane = tid & 31, w = tid >> 5;
    const float* Cs = (const float*)(sm + SM_C);
    float4 bc = *(const float4*)(bC + lane * 4);
    float s0 = 0.f, s1 = 0.f, s2 = 0.f, s3 = 0.f;
    float q0 = 0.f, q1 = 0.f, q2 = 0.f, q3 = 0.f;
#pragma unroll
    for (int k = 0; k < 8; k++) {
        int m = w * 8 + k;
        int ei = e0 + m;
        if (ei < E) {
            int rv = rI[m], cv = cI[m];
            float4 cc = *(const float4*)(Cs + m * CSTRIDE + lane * 4);
            float4 ah = *(const float4*)(g_Ah + (size_t)cv * H + lane * 4);
            float4 bh = *(const float4*)(g_Bh + (size_t)rv * H + lane * 4);
            float4 vn = *(const float4*)(g_Vn + (size_t)cv * H + lane * 4);
            float4 x;
            x.x = cc.x + bc.x + ah.x + bh.x;
            x.y = cc.y + bc.y + ah.y + bh.y;
            x.z = cc.z + bc.z + ah.z + bh.z;
            x.w = cc.w + bc.w + ah.w + bh.w;
            *(float4*)(g_epre + (size_t)ei * H + lane * 4) = x;
            float ga = vn.x / (1.f + __expf(-x.x));
            float gb = vn.y / (1.f + __expf(-x.y));
            float gc = vn.z / (1.f + __expf(-x.z));
            float gd = vn.w / (1.f + __expf(-x.w));
            float* agp = g_agg + (size_t)rv * H + lane * 4;
            redv2(agp, ga, gb);
            redv2(agp + 2, gc, gd);
            s0 += x.x; s1 += x.y; s2 += x.z; s3 += x.w;
            q0 += x.x * x.x; q1 += x.y * x.y; q2 += x.z * x.z; q3 += x.w * x.w;
        }
    }
    float* sr = (float*)(sm + SM_SRED);
    float* qr = (float*)(sm + SM_QRED);
    *(float4*)(sr + w * 128 + lane * 4) = make_float4(s0, s1, s2, s3);
    *(float4*)(qr + w * 128 + lane * 4) = make_float4(q0, q1, q2, q3);
    __syncthreads();
    if (tid < 128) {
        float a = 0.f, b = 0.f;
#pragma unroll
        for (int ww = 0; ww < 16; ww++) { a += sr[ww * 128 + tid]; b += qr[ww * 128 + tid]; }
        atomicAdd(&g_stats[2 * H + tid], a);
        atomicAdd(&g_stats[3 * H + tid], b);
    }
}

// ---------------------------------------------------------------------------
__global__ __launch_bounds__(NT, 1) void k_edgeout(
        const float* __restrict__ e, float* __restrict__ out, int E) {
    extern __shared__ char sm[];
    uint32_t sb = smem_u32(sm);
    int tid = threadIdx.x;
    int e0 = blockIdx.x * 128;
    int nrows = E - e0; if (nrows > 128) nrows = 128;

    copy_B(5, sm + SM_B);
    load_A_bn(g_epre + (size_t)e0 * H, nrows, sm + SM_A);
    __syncthreads();

    float C[8][4];
    gemm_compute(sb + SM_A, sb + SM_B, C);
    __syncthreads();
    gemm_storeC((float*)(sm + SM_C), C);
    __syncthreads();

    int lane = tid & 31, w = tid >> 5;
    const float* Cs = (const float*)(sm + SM_C);
    float4 cv4 = *(const float4*)(g_cvec + lane * 4);
#pragma unroll
    for (int k = 0; k < 8; k++) {
        int m = w * 8 + k;
        int ei = e0 + m;
        if (ei < E) {
            float4 cc = *(const float4*)(Cs + m * CSTRIDE + lane * 4);
            float4 ev = *(const float4*)(e + (size_t)ei * H + lane * 4);
            float4 o;
            o.x = ev.x + cc.x + cv4.x;
            o.y = ev.y + cc.y + cv4.y;
            o.z = ev.z + cc.z + cv4.z;
            o.w = ev.w + cc.w + cv4.w;
            *(float4*)(out + (size_t)ei * H + lane * 4) = o;
        }
    }
}

// ---------------------------------------------------------------------------
__global__ void k_nstats(int rows) {
    int tid = threadIdx.x;
    int cg = tid & 31, wr = tid >> 5;
    float4 s = make_float4(0.f, 0.f, 0.f, 0.f);
    float4 qq = make_float4(0.f, 0.f, 0.f, 0.f);
    const float4* s4 = (const float4*)g_agg;
    for (int r = blockIdx.x * 8 + wr; r < rows; r += gridDim.x * 8) {
        float4 x = s4[(size_t)r * 32 + cg];
        s.x += x.x; s.y += x.y; s.z += x.z; s.w += x.w;
        qq.x += x.x * x.x; qq.y += x.y * x.y; qq.z += x.z * x.z; qq.w += x.w * x.w;
    }
    __shared__ float sh1[8][128], sh2[8][128];
    *(float4*)&sh1[wr][cg * 4] = s;
    *(float4*)&sh2[wr][cg * 4] = qq;
    __syncthreads();
    if (tid < 128) {
        float a = 0.f, b = 0.f;
#pragma unroll
        for (int ww = 0; ww < 8; ww++) { a += sh1[ww][tid]; b += sh2[ww][tid]; }
        atomicAdd(&g_stats[tid], a);
        atomicAdd(&g_stats[H + tid], b);
    }
}

// ---------------------------------------------------------------------------
__global__ void k_finalize(const float* __restrict__ gh, const float* __restrict__ bh,
                           const float* __restrict__ ge, const float* __restrict__ be,
                           int V, int E) {
    int j = threadIdx.x;
    float invV = 1.0f / (float)V, invE = 1.0f / (float)E;
    float mh = g_stats[j] * invV;
    float vh = g_stats[H + j] * invV - mh * mh;
    float sc = gh[j] * rsqrtf(vh + 1e-5f);
    g_scale_h[j] = sc;
    g_shift_h[j] = bh[j] - mh * sc;
    float me = g_stats[2 * H + j] * invE;
    float ve = g_stats[3 * H + j] * invE - me * me;
    float se = ge[j] * rsqrtf(ve + 1e-5f);
    g_scale_e[j] = se;
    g_shift_e[j] = be[j] - me * se;
}

// ---------------------------------------------------------------------------
__global__ void k_nodeout(const float* __restrict__ h, float* __restrict__ out, int V) {
    int idx = blockIdx.x * blockDim.x + threadIdx.x;
    int total = V * (H / 4);
    if (idx >= total) return;
    int j = (idx & 31) * 4;
    float4 a  = *(const float4*)&g_agg[(size_t)idx * 4];
    float4 sc = *(const float4*)&g_scale_h[j];
    float4 sh = *(const float4*)&g_shift_h[j];
    float4 hv = *(const float4*)&h[(size_t)idx * 4];
    float4 r;
    r.x = hv.x + fmaxf(fmaf(a.x, sc.x, sh.x), 0.f);
    r.y = hv.y + fmaxf(fmaf(a.y, sc.y, sh.y), 0.f);
    r.z = hv.z + fmaxf(fmaf(a.z, sc.z, sh.z), 0.f);
    r.w = hv.w + fmaxf(fmaf(a.w, sc.w, sh.w), 0.f);
    *(float4*)&out[(size_t)idx * 4] = r;
}

// ---------------------------------------------------------------------------
extern "C" void kernel_launch(void* const* d_in, const int* in_sizes, int n_in,
                              void* d_out, int out_size) {
    const float* h        = (const float*)d_in[0];
    const float* e        = (const float*)d_in[1];
    const float* time_emb = (const float*)d_in[2];
    const int*   eidx     = (const int*)d_in[3];
    const float* WU = (const float*)d_in[4];  const float* bU = (const float*)d_in[5];
    const float* WV = (const float*)d_in[6];  const float* bV = (const float*)d_in[7];
    const float* WA = (const float*)d_in[8];  const float* bA = (const float*)d_in[9];
    const float* WB = (const float*)d_in[10]; const float* bB = (const float*)d_in[11];
    const float* WC = (const float*)d_in[12]; const float* bC = (const float*)d_in[13];
    const float* Wt = (const float*)d_in[14]; const float* bt = (const float*)d_in[15];
    const float* Wo = (const float*)d_in[16]; const float* bo = (const float*)d_in[17];
    const float* gh = (const float*)d_in[18]; const float* bh = (const float*)d_in[19];
    const float* ge = (const float*)d_in[20]; const float* be = (const float*)d_in[21];

    int V = in_sizes[0] / H;
    int E = in_sizes[3] / 2;

    float* xout = (float*)d_out;
    float* eout = xout + (size_t)V * H;

    cudaFuncSetAttribute(k_node,    cudaFuncAttributeMaxDynamicSharedMemorySize, SMEM_BYTES);
    cudaFuncSetAttribute(k_edge,    cudaFuncAttributeMaxDynamicSharedMemorySize, SMEM_BYTES);
    cudaFuncSetAttribute(k_edgeout, cudaFuncAttributeMaxDynamicSharedMemorySize, SMEM_BYTES);

    int vTiles = (V + 127) / 128;
    int eTiles = (E + 127) / 128;

    k_init<<<1, 128>>>(time_emb, Wt, bt, Wo, bo);
    k_prep<<<6, 256>>>(WU, WV, WA, WB, WC, Wo);
    k_node<<<dim3(vTiles, 4), NT, SMEM_BYTES>>>(h, bU, bV, bA, bB, V);
    k_edge<<<eTiles, NT, SMEM_BYTES>>>(e, bC, eidx, E);
    k_nstats<<<512, 256>>>(V);
    k_finalize<<<1, 128>>>(gh, bh, ge, be, V, E);
    k_nodeout<<<(V * (H / 4) + 255) / 256, 256>>>(h, xout, V);
    k_edgeout<<<eTiles, NT, SMEM_BYTES>>>(e, eout, E);
}

// round 6
// speedup vs baseline: 2.4452x; 1.1740x over previous
#include <cuda_runtime.h>
#include <cuda_bf16.h>
#include <cstdint>

// ---------------------------------------------------------------------------
// DAGCondGNNEncoder (sm_103 HMMA path): split-bf16 mma.sync GEMMs.
// R6: persistent CTAs (B loaded once), cp.async A staging pipeline,
//     register-resident BN stats.
// ---------------------------------------------------------------------------

#define H 128
#define VMAX 50000
#define EMAX 625000
#define NT 512

// ---- device scratch ----
__device__ __align__(16) float g_agg[(size_t)VMAX * H];
__device__ __align__(16) float g_Vn [(size_t)VMAX * H];
__device__ __align__(16) float g_Ah [(size_t)VMAX * H];
__device__ __align__(16) float g_Bh [(size_t)VMAX * H];
__device__ __align__(16) float g_epre[(size_t)EMAX * H];
__device__ __align__(16) float g_stats[4 * H];
__device__ __align__(16) float g_cvec[H];
__device__ __align__(16) float g_scale_h[H];
__device__ __align__(16) float g_shift_h[H];
__device__ __align__(16) float g_scale_e[H];
__device__ __align__(16) float g_shift_e[H];
__device__ __align__(16) unsigned char g_Bimg[6 * 65536];

// ---- smem layout ----
//  [0..2048)      idx double buffer (rI/cI x2)
//  [2048..3072)   BN scale/shift copy (k_edgeout)
//  [4096..69632)  A hi (32KB) + A lo (32KB)
//  [4096..71680)  C fp32 tile (CSTRIDE 132) -- overlays A after MMA
//  [71680..137216) cp.async staging (raw fp32 A tile) ; stats red at end
//  [137216..202752) B hi/lo
#define SM_SC    2048
#define SM_SH    2560
#define SM_A     4096
#define SM_C     4096
#define CSTRIDE  132
#define SM_STAGE 71680
#define SM_B     137216
#define SMEM_BYTES 202752

// ---- helpers ----
__device__ __forceinline__ uint32_t smem_u32(const void* p) {
    uint32_t a;
    asm("{ .reg .u64 t; cvta.to.shared.u64 t, %1; cvt.u32.u64 %0, t; }" : "=r"(a) : "l"(p));
    return a;
}
__device__ __forceinline__ uint32_t bpack(float a, float b) {
    __nv_bfloat162 t = __floats2bfloat162_rn(a, b);
    return *reinterpret_cast<uint32_t*>(&t);
}
__device__ __forceinline__ float bres(float a) {
    __nv_bfloat16 hh = __float2bfloat16_rn(a);
    return a - __bfloat162float(hh);
}
__device__ __forceinline__ void storeA8(char* hiP, char* loP, uint32_t off, const float* v) {
    uint4 hv, lv;
    hv.x = bpack(v[0], v[1]); hv.y = bpack(v[2], v[3]);
    hv.z = bpack(v[4], v[5]); hv.w = bpack(v[6], v[7]);
    lv.x = bpack(bres(v[0]), bres(v[1])); lv.y = bpack(bres(v[2]), bres(v[3]));
    lv.z = bpack(bres(v[4]), bres(v[5])); lv.w = bpack(bres(v[6]), bres(v[7]));
    *(uint4*)(hiP + off) = hv;
    *(uint4*)(loP + off) = lv;
}
__device__ __forceinline__ void ldsm4(uint32_t r[4], uint32_t addr) {
    asm volatile("ldmatrix.sync.aligned.m8n8.x4.shared.b16 {%0,%1,%2,%3}, [%4];"
        : "=r"(r[0]), "=r"(r[1]), "=r"(r[2]), "=r"(r[3]) : "r"(addr));
}
__device__ __forceinline__ void mma16816(float c[4], const uint32_t a[4], uint32_t b0, uint32_t b1) {
    asm volatile("mma.sync.aligned.m16n8k16.row.col.f32.bf16.bf16.f32 "
        "{%0,%1,%2,%3},{%4,%5,%6,%7},{%8,%9},{%0,%1,%2,%3};"
        : "+f"(c[0]), "+f"(c[1]), "+f"(c[2]), "+f"(c[3])
        : "r"(a[0]), "r"(a[1]), "r"(a[2]), "r"(a[3]), "r"(b0), "r"(b1));
}
__device__ __forceinline__ void redv2(float* p, float a, float b) {
    asm volatile("red.global.add.v2.f32 [%0], {%1, %2};" :: "l"(p), "f"(a), "f"(b) : "memory");
}
__device__ __forceinline__ void pf_l2(const void* p) {
    asm volatile("prefetch.global.L2 [%0];" :: "l"(p));
}
__device__ __forceinline__ void cpa16(uint32_t dst, const void* src, int pred) {
    asm volatile("{ .reg .pred p; setp.ne.b32 p, %2, 0;\n\t"
        "@p cp.async.cg.shared.global [%0], [%1], 16; }"
        :: "r"(dst), "l"(src), "r"(pred));
}
#define CP_COMMIT() asm volatile("cp.async.commit_group;" ::: "memory")
#define CP_WAIT0()  asm volatile("cp.async.wait_group 0;" ::: "memory")

// ---- GEMM core: 128x128x128 tile, 16 warps, warp tile 16x64 ----
__device__ __forceinline__ void gemm_compute(uint32_t sAu, uint32_t sBu, float C[8][4]) {
    int tid = threadIdx.x, lane = tid & 31, wid = tid >> 5;
    int rm = (wid & 7) * 16, cn = (wid >> 3) * 64;
#pragma unroll
    for (int nf = 0; nf < 8; nf++)
#pragma unroll
        for (int q = 0; q < 4; q++) C[nf][q] = 0.f;

    int xr = lane & 7;
    int arow = xr + ((lane >> 3) & 1) * 8;
    int ahs = lane >> 4;
    int bhs = (lane >> 3) & 1;
    int bnr = xr + (lane >> 4) * 8;
    uint32_t aB = sAu + (uint32_t)(rm + arow) * 256;
    uint32_t bB[4];
#pragma unroll
    for (int g = 0; g < 4; g++) bB[g] = sBu + (uint32_t)(cn + g * 16 + bnr) * 256;

#pragma unroll
    for (int ks = 0; ks < 8; ks++) {
        uint32_t oA = (uint32_t)(((ks * 2 + ahs) ^ xr) << 4);
        uint32_t oB = (uint32_t)(((ks * 2 + bhs) ^ xr) << 4);
        uint32_t aH[4], aL[4];
        ldsm4(aH, aB + oA);
        ldsm4(aL, aB + 32768 + oA);
        uint32_t bH[4][4], bL[4][4];
#pragma unroll
        for (int g = 0; g < 4; g++) {
            ldsm4(bH[g], bB[g] + oB);
            ldsm4(bL[g], bB[g] + 32768 + oB);
        }
#pragma unroll
        for (int g = 0; g < 4; g++) {
            mma16816(C[2*g],   aH, bH[g][0], bH[g][1]);
            mma16816(C[2*g+1], aH, bH[g][2], bH[g][3]);
            mma16816(C[2*g],   aH, bL[g][0], bL[g][1]);
            mma16816(C[2*g+1], aH, bL[g][2], bL[g][3]);
            mma16816(C[2*g],   aL, bH[g][0], bH[g][1]);
            mma16816(C[2*g+1], aL, bH[g][2], bH[g][3]);
        }
    }
}

__device__ __forceinline__ void gemm_storeC(float* Cs, float C[8][4]) {
    int tid = threadIdx.x, lane = tid & 31, wid = tid >> 5;
    int rm = (wid & 7) * 16, cn = (wid >> 3) * 64;
    int r = lane >> 2, c2 = 2 * (lane & 3);
#pragma unroll
    for (int nf = 0; nf < 8; nf++) {
        int col = cn + nf * 8 + c2;
        *(float2*)(Cs + (rm + r) * CSTRIDE + col)     = make_float2(C[nf][0], C[nf][1]);
        *(float2*)(Cs + (rm + r + 8) * CSTRIDE + col) = make_float2(C[nf][2], C[nf][3]);
    }
}

// ---- pipeline pieces ----
__device__ __forceinline__ void stage_A(uint32_t sb, const float* src, int r0, int limit) {
    int tid = threadIdx.x;
    uint32_t dst = sb + SM_STAGE;
#pragma unroll
    for (int it = 0; it < 8; it++) {
        int c = it * NT + tid;
        int row = c >> 5, part = c & 31;
        cpa16(dst + c * 16, src + (size_t)(r0 + row) * H + part * 4, (r0 + row) < limit);
    }
    CP_COMMIT();
}

__device__ __forceinline__ void convert_plain(char* sm) {
    const float* stg = (const float*)(sm + SM_STAGE);
    char* sA = sm + SM_A;
    int tid = threadIdx.x;
#pragma unroll
    for (int it = 0; it < 4; it++) {
        int s = it * NT + tid;
        int row = s >> 4, kseg = s & 15;
        const float4* p = (const float4*)(stg + row * 128 + kseg * 8);
        float4 f0 = p[0], f1 = p[1];
        float v[8] = {f0.x, f0.y, f0.z, f0.w, f1.x, f1.y, f1.z, f1.w};
        uint32_t off = (uint32_t)row * 256 + (uint32_t)((kseg ^ (row & 7)) << 4);
        storeA8(sA, sA + 32768, off, v);
    }
}

__device__ __forceinline__ void convert_bn(char* sm) {
    const float* stg = (const float*)(sm + SM_STAGE);
    const float4* sc4 = (const float4*)(sm + SM_SC);
    const float4* sh4 = (const float4*)(sm + SM_SH);
    char* sA = sm + SM_A;
    int tid = threadIdx.x;
#pragma unroll
    for (int it = 0; it < 4; it++) {
        int s = it * NT + tid;
        int row = s >> 4, kseg = s & 15;
        const float4* p = (const float4*)(stg + row * 128 + kseg * 8);
        float4 f0 = p[0], f1 = p[1];
        float4 s0 = sc4[kseg * 2], s1 = sc4[kseg * 2 + 1];
        float4 t0 = sh4[kseg * 2], t1 = sh4[kseg * 2 + 1];
        float v[8];
        v[0] = fmaxf(fmaf(f0.x, s0.x, t0.x), 0.f);
        v[1] = fmaxf(fmaf(f0.y, s0.y, t0.y), 0.f);
        v[2] = fmaxf(fmaf(f0.z, s0.z, t0.z), 0.f);
        v[3] = fmaxf(fmaf(f0.w, s0.w, t0.w), 0.f);
        v[4] = fmaxf(fmaf(f1.x, s1.x, t1.x), 0.f);
        v[5] = fmaxf(fmaf(f1.y, s1.y, t1.y), 0.f);
        v[6] = fmaxf(fmaf(f1.z, s1.z, t1.z), 0.f);
        v[7] = fmaxf(fmaf(f1.w, s1.w, t1.w), 0.f);
        uint32_t off = (uint32_t)row * 256 + (uint32_t)((kseg ^ (row & 7)) << 4);
        storeA8(sA, sA + 32768, off, v);
    }
}

__device__ __forceinline__ void copy_B(int widx, char* sB) {
    const uint4* g = (const uint4*)(g_Bimg + (size_t)widx * 65536);
    uint4* d = (uint4*)sB;
    int tid = threadIdx.x;
#pragma unroll
    for (int it = 0; it < 8; it++) d[it * NT + tid] = g[it * NT + tid];
}

__device__ __forceinline__ void load_idx(char* sm, const int* eidx, int t, int E, int p) {
    int tid = threadIdx.x;
    int e0 = t * 128;
    if (tid < 128) {
        int ei = e0 + tid;
        ((int*)(sm + p * 1024))[tid] = (ei < E) ? eidx[ei] : 0;
    } else if (tid < 256) {
        int q = tid - 128, ei = e0 + q;
        ((int*)(sm + p * 1024 + 512))[q] = (ei < E) ? eidx[(size_t)E + ei] : 0;
    }
}

__device__ __forceinline__ void prefetch_gathers(char* sm, int p) {
    const int* rI = (const int*)(sm + p * 1024);
    const int* cI = (const int*)(sm + p * 1024 + 512);
    int tid = threadIdx.x;
#pragma unroll
    for (int i = tid; i < 1536; i += NT) {
        int m = i & 127, sel = i >> 7;
        int arr = sel >> 2, part = (sel & 3) * 32;
        const float* ptr;
        if (arr == 0)      ptr = g_Ah + (size_t)cI[m] * H + part;
        else if (arr == 1) ptr = g_Bh + (size_t)rI[m] * H + part;
        else               ptr = g_Vn + (size_t)cI[m] * H + part;
        pf_l2(ptr);
    }
}

// ---------------------------------------------------------------------------
__global__ void k_init(const float* __restrict__ time_emb,
                       const float* __restrict__ Wt, const float* __restrict__ bt,
                       const float* __restrict__ Wo, const float* __restrict__ bo) {
    int j = threadIdx.x;
    for (int i = j; i < 4 * H; i += H) g_stats[i] = 0.0f;
    __shared__ float tv[H];
    float acc = bt[j];
    for (int k = 0; k < H; k++) acc += time_emb[k] * Wt[k * H + j];
    tv[j] = acc;
    __syncthreads();
    float c = bo[j];
    for (int k = 0; k < H; k++) c += tv[k] * Wo[k * H + j];
    g_cvec[j] = c;
}

// ---------------------------------------------------------------------------
__global__ void k_prep(const float* __restrict__ WU, const float* __restrict__ WV,
                       const float* __restrict__ WA, const float* __restrict__ WB,
                       const float* __restrict__ WC, const float* __restrict__ Wo) {
    const float* Ws[6] = {WU, WV, WA, WB, WC, Wo};
    const float* W = Ws[blockIdx.x];
    unsigned char* img = g_Bimg + (size_t)blockIdx.x * 65536;
    int tid = threadIdx.x;
    for (int it = 0; it < 64; it++) {
        int idx = it * 256 + tid;
        int k = idx >> 7, n = idx & 127;
        float v = W[k * H + n];
        __nv_bfloat16 hi = __float2bfloat16_rn(v);
        __nv_bfloat16 lo = __float2bfloat16_rn(v - __bfloat162float(hi));
        uint32_t off = (uint32_t)n * 256 + (uint32_t)((((k >> 3) ^ (n & 7))) << 4) + (k & 7) * 2;
        *(__nv_bfloat16*)(img + off) = hi;
        *(__nv_bfloat16*)(img + 32768 + off) = lo;
    }
}

// ---------------------------------------------------------------------------
// k_node (persistent per widx): grid (gx, 4)
// ---------------------------------------------------------------------------
__global__ __launch_bounds__(NT, 1) void k_node(
        const float* __restrict__ h,
        const float* __restrict__ bU, const float* __restrict__ bV,
        const float* __restrict__ bA, const float* __restrict__ bB,
        int V, int nTiles) {
    extern __shared__ char sm[];
    uint32_t sb = smem_u32(sm);
    int tid = threadIdx.x;
    int widx = blockIdx.y;

    copy_B(widx, sm + SM_B);
    float* out; const float* bias;
    switch (widx) {
        case 0:  out = g_agg; bias = bU; break;
        case 1:  out = g_Vn;  bias = bV; break;
        case 2:  out = g_Ah;  bias = bA; break;
        default: out = g_Bh;  bias = bB; break;
    }

    int t = blockIdx.x;
    if (t >= nTiles) return;
    // prologue: stage + convert first tile
    stage_A(sb, h, t * 128, V);
    CP_WAIT0(); __syncthreads();
    convert_plain(sm);
    __syncthreads();

    while (t < nTiles) {
        int nxt = t + gridDim.x;
        if (nxt < nTiles) stage_A(sb, h, nxt * 128, V);

        float C[8][4];
        gemm_compute(sb + SM_A, sb + SM_B, C);
        __syncthreads();
        gemm_storeC((float*)(sm + SM_C), C);
        __syncthreads();

        int r0 = t * 128;
        const float* Cs = (const float*)(sm + SM_C);
#pragma unroll
        for (int it = 0; it < 8; it++) {
            int idx = it * NT + tid;
            int row = idx >> 5, cs = idx & 31;
            if (r0 + row < V) {
                float4 c = *(const float4*)(Cs + row * CSTRIDE + cs * 4);
                float4 b = *(const float4*)(bias + cs * 4);
                c.x += b.x; c.y += b.y; c.z += b.z; c.w += b.w;
                *(float4*)(out + (size_t)(r0 + row) * H + cs * 4) = c;
            }
        }
        CP_WAIT0();
        __syncthreads();
        if (nxt < nTiles) { convert_plain(sm); }
        __syncthreads();
        t = nxt;
    }
}

// ---------------------------------------------------------------------------
// k_edge (persistent): grid 148
// ---------------------------------------------------------------------------
__global__ __launch_bounds__(NT, 1) void k_edge(
        const float* __restrict__ e, const float* __restrict__ bC,
        const int* __restrict__ eidx, int E, int nTiles) {
    extern __shared__ char sm[];
    uint32_t sb = smem_u32(sm);
    int tid = threadIdx.x, lane = tid & 31, w = tid >> 5;

    copy_B(4, sm + SM_B);
    float4 bc = *(const float4*)(bC + lane * 4);
    float ss[4] = {0.f, 0.f, 0.f, 0.f}, sq[4] = {0.f, 0.f, 0.f, 0.f};

    int t = blockIdx.x, p = 0;
    if (t < nTiles) {
        load_idx(sm, eidx, t, E, 0);
        stage_A(sb, e, t * 128, E);
        CP_WAIT0(); __syncthreads();
        convert_plain(sm);
        prefetch_gathers(sm, 0);
        __syncthreads();

        while (t < nTiles) {
            int nxt = t + gridDim.x;
            if (nxt < nTiles) {
                stage_A(sb, e, nxt * 128, E);
                load_idx(sm, eidx, nxt, E, p ^ 1);
            }

            float C[8][4];
            gemm_compute(sb + SM_A, sb + SM_B, C);
            __syncthreads();
            gemm_storeC((float*)(sm + SM_C), C);
            __syncthreads();

            int e0 = t * 128;
            const int* rI = (const int*)(sm + p * 1024);
            const int* cI = (const int*)(sm + p * 1024 + 512);
            const float* Cs = (const float*)(sm + SM_C);
#pragma unroll
            for (int k = 0; k < 8; k++) {
                int m = w * 8 + k;
                int ei = e0 + m;
                if (ei < E) {
                    int rv = rI[m], cv = cI[m];
                    float4 cc = *(const float4*)(Cs + m * CSTRIDE + lane * 4);
                    float4 ah = *(const float4*)(g_Ah + (size_t)cv * H + lane * 4);
                    float4 bh = *(const float4*)(g_Bh + (size_t)rv * H + lane * 4);
                    float4 vn = *(const float4*)(g_Vn + (size_t)cv * H + lane * 4);
                    float4 x;
                    x.x = cc.x + bc.x + ah.x + bh.x;
                    x.y = cc.y + bc.y + ah.y + bh.y;
                    x.z = cc.z + bc.z + ah.z + bh.z;
                    x.w = cc.w + bc.w + ah.w + bh.w;
                    *(float4*)(g_epre + (size_t)ei * H + lane * 4) = x;
                    float ga = vn.x / (1.f + __expf(-x.x));
                    float gb = vn.y / (1.f + __expf(-x.y));
                    float gc = vn.z / (1.f + __expf(-x.z));
                    float gd = vn.w / (1.f + __expf(-x.w));
                    float* agp = g_agg + (size_t)rv * H + lane * 4;
                    redv2(agp, ga, gb);
                    redv2(agp + 2, gc, gd);
                    ss[0] += x.x; ss[1] += x.y; ss[2] += x.z; ss[3] += x.w;
                    sq[0] += x.x * x.x; sq[1] += x.y * x.y;
                    sq[2] += x.z * x.z; sq[3] += x.w * x.w;
                }
            }
            if (nxt < nTiles) prefetch_gathers(sm, p ^ 1);
            CP_WAIT0();
            __syncthreads();
            if (nxt < nTiles) convert_plain(sm);
            __syncthreads();
            t = nxt; p ^= 1;
        }
    }

    // block-reduce register stats (reuse STAGE region)
    float* sr = (float*)(sm + SM_STAGE);
    float* qr = sr + 2048;
    *(float4*)(sr + w * 128 + lane * 4) = make_float4(ss[0], ss[1], ss[2], ss[3]);
    *(float4*)(qr + w * 128 + lane * 4) = make_float4(sq[0], sq[1], sq[2], sq[3]);
    __syncthreads();
    if (tid < 128) {
        float a = 0.f, b = 0.f;
#pragma unroll
        for (int ww = 0; ww < 16; ww++) { a += sr[ww * 128 + tid]; b += qr[ww * 128 + tid]; }
        atomicAdd(&g_stats[2 * H + tid], a);
        atomicAdd(&g_stats[3 * H + tid], b);
    }
}

// ---------------------------------------------------------------------------
// k_edgeout (persistent): grid 148
// ---------------------------------------------------------------------------
__global__ __launch_bounds__(NT, 1) void k_edgeout(
        const float* __restrict__ e, float* __restrict__ out, int E, int nTiles) {
    extern __shared__ char sm[];
    uint32_t sb = smem_u32(sm);
    int tid = threadIdx.x, lane = tid & 31, w = tid >> 5;

    copy_B(5, sm + SM_B);
    if (tid < 128) {
        ((float*)(sm + SM_SC))[tid] = g_scale_e[tid];
        ((float*)(sm + SM_SH))[tid] = g_shift_e[tid];
    }
    float4 cv4 = *(const float4*)(g_cvec + lane * 4);

    int t = blockIdx.x;
    if (t >= nTiles) return;

    stage_A(sb, g_epre, t * 128, E);
    CP_WAIT0(); __syncthreads();
    convert_bn(sm);
    __syncthreads();

    while (t < nTiles) {
        int nxt = t + gridDim.x;
        if (nxt < nTiles) stage_A(sb, g_epre, nxt * 128, E);

        float C[8][4];
        gemm_compute(sb + SM_A, sb + SM_B, C);
        __syncthreads();
        gemm_storeC((float*)(sm + SM_C), C);
        __syncthreads();

        int e0 = t * 128;
        const float* Cs = (const float*)(sm + SM_C);
#pragma unroll
        for (int k = 0; k < 8; k++) {
            int m = w * 8 + k;
            int ei = e0 + m;
            if (ei < E) {
                float4 cc = *(const float4*)(Cs + m * CSTRIDE + lane * 4);
                float4 ev = *(const float4*)(e + (size_t)ei * H + lane * 4);
                float4 o;
                o.x = ev.x + cc.x + cv4.x;
                o.y = ev.y + cc.y + cv4.y;
                o.z = ev.z + cc.z + cv4.z;
                o.w = ev.w + cc.w + cv4.w;
                *(float4*)(out + (size_t)ei * H + lane * 4) = o;
            }
        }
        CP_WAIT0();
        __syncthreads();
        if (nxt < nTiles) convert_bn(sm);
        __syncthreads();
        t = nxt;
    }
}

// ---------------------------------------------------------------------------
__global__ void k_nstats(int rows) {
    int tid = threadIdx.x;
    int cg = tid & 31, wr = tid >> 5;
    float4 s = make_float4(0.f, 0.f, 0.f, 0.f);
    float4 qq = make_float4(0.f, 0.f, 0.f, 0.f);
    const float4* s4 = (const float4*)g_agg;
    for (int r = blockIdx.x * 8 + wr; r < rows; r += gridDim.x * 8) {
        float4 x = s4[(size_t)r * 32 + cg];
        s.x += x.x; s.y += x.y; s.z += x.z; s.w += x.w;
        qq.x += x.x * x.x; qq.y += x.y * x.y; qq.z += x.z * x.z; qq.w += x.w * x.w;
    }
    __shared__ float sh1[8][128], sh2[8][128];
    *(float4*)&sh1[wr][cg * 4] = s;
    *(float4*)&sh2[wr][cg * 4] = qq;
    __syncthreads();
    if (tid < 128) {
        float a = 0.f, b = 0.f;
#pragma unroll
        for (int ww = 0; ww < 8; ww++) { a += sh1[ww][tid]; b += sh2[ww][tid]; }
        atomicAdd(&g_stats[tid], a);
        atomicAdd(&g_stats[H + tid], b);
    }
}

// ---------------------------------------------------------------------------
__global__ void k_finalize(const float* __restrict__ gh, const float* __restrict__ bh,
                           const float* __restrict__ ge, const float* __restrict__ be,
                           int V, int E) {
    int j = threadIdx.x;
    float invV = 1.0f / (float)V, invE = 1.0f / (float)E;
    float mh = g_stats[j] * invV;
    float vh = g_stats[H + j] * invV - mh * mh;
    float sc = gh[j] * rsqrtf(vh + 1e-5f);
    g_scale_h[j] = sc;
    g_shift_h[j] = bh[j] - mh * sc;
    float me = g_stats[2 * H + j] * invE;
    float ve = g_stats[3 * H + j] * invE - me * me;
    float se = ge[j] * rsqrtf(ve + 1e-5f);
    g_scale_e[j] = se;
    g_shift_e[j] = be[j] - me * se;
}

// ---------------------------------------------------------------------------
__global__ void k_nodeout(const float* __restrict__ h, float* __restrict__ out, int V) {
    int idx = blockIdx.x * blockDim.x + threadIdx.x;
    int total = V * (H / 4);
    if (idx >= total) return;
    int j = (idx & 31) * 4;
    float4 a  = *(const float4*)&g_agg[(size_t)idx * 4];
    float4 sc = *(const float4*)&g_scale_h[j];
    float4 sh = *(const float4*)&g_shift_h[j];
    float4 hv = *(const float4*)&h[(size_t)idx * 4];
    float4 r;
    r.x = hv.x + fmaxf(fmaf(a.x, sc.x, sh.x), 0.f);
    r.y = hv.y + fmaxf(fmaf(a.y, sc.y, sh.y), 0.f);
    r.z = hv.z + fmaxf(fmaf(a.z, sc.z, sh.z), 0.f);
    r.w = hv.w + fmaxf(fmaf(a.w, sc.w, sh.w), 0.f);
    *(float4*)&out[(size_t)idx * 4] = r;
}

// ---------------------------------------------------------------------------
extern "C" void kernel_launch(void* const* d_in, const int* in_sizes, int n_in,
                              void* d_out, int out_size) {
    const float* h        = (const float*)d_in[0];
    const float* e        = (const float*)d_in[1];
    const float* time_emb = (const float*)d_in[2];
    const int*   eidx     = (const int*)d_in[3];
    const float* WU = (const float*)d_in[4];  const float* bU = (const float*)d_in[5];
    const float* WV = (const float*)d_in[6];  const float* bV = (const float*)d_in[7];
    const float* WA = (const float*)d_in[8];  const float* bA = (const float*)d_in[9];
    const float* WB = (const float*)d_in[10]; const float* bB = (const float*)d_in[11];
    const float* WC = (const float*)d_in[12]; const float* bC = (const float*)d_in[13];
    const float* Wt = (const float*)d_in[14]; const float* bt = (const float*)d_in[15];
    const float* Wo = (const float*)d_in[16]; const float* bo = (const float*)d_in[17];
    const float* gh = (const float*)d_in[18]; const float* bh = (const float*)d_in[19];
    const float* ge = (const float*)d_in[20]; const float* be = (const float*)d_in[21];

    int V = in_sizes[0] / H;
    int E = in_sizes[3] / 2;

    float* xout = (float*)d_out;
    float* eout = xout + (size_t)V * H;

    cudaFuncSetAttribute(k_node,    cudaFuncAttributeMaxDynamicSharedMemorySize, SMEM_BYTES);
    cudaFuncSetAttribute(k_edge,    cudaFuncAttributeMaxDynamicSharedMemorySize, SMEM_BYTES);
    cudaFuncSetAttribute(k_edgeout, cudaFuncAttributeMaxDynamicSharedMemorySize, SMEM_BYTES);

    int vTiles = (V + 127) / 128;
    int eTiles = (E + 127) / 128;
    int gxNode = vTiles < 37 ? vTiles : 37;
    int gxEdge = eTiles < 148 ? eTiles : 148;

    k_init<<<1, 128>>>(time_emb, Wt, bt, Wo, bo);
    k_prep<<<6, 256>>>(WU, WV, WA, WB, WC, Wo);
    k_node<<<dim3(gxNode, 4), NT, SMEM_BYTES>>>(h, bU, bV, bA, bB, V, vTiles);
    k_edge<<<gxEdge, NT, SMEM_BYTES>>>(e, bC, eidx, E, eTiles);
    k_nstats<<<512, 256>>>(V);
    k_finalize<<<1, 128>>>(gh, bh, ge, be, V, E);
    k_nodeout<<<(V * (H / 4) + 255) / 256, 256>>>(h, xout, V);
    k_edgeout<<<gxEdge, NT, SMEM_BYTES>>>(e, eout, E, eTiles);
}

// round 7
// speedup vs baseline: 2.4806x; 1.0145x over previous
#include <cuda_runtime.h>
#include <cuda_bf16.h>
#include <cstdint>

// ---------------------------------------------------------------------------
// DAGCondGNNEncoder (sm_103 HMMA path): split-bf16 mma.sync GEMMs.
// R7: index-role-packed node arrays (colpack=[Vn|Ah], rowpack=[Bh|agg]) for
//     gather/scatter locality + red.global.add.v4.f32 epilogue atomics.
// ---------------------------------------------------------------------------

#define H 128
#define VMAX 50000
#define EMAX 625000
#define NT 512

// ---- device scratch ----
__device__ __align__(16) float g_colpack[(size_t)VMAX * 256];  // [Vn | Ah]
__device__ __align__(16) float g_rowpack[(size_t)VMAX * 256];  // [Bh | agg]
__device__ __align__(16) float g_epre[(size_t)EMAX * H];
__device__ __align__(16) float g_stats[4 * H];
__device__ __align__(16) float g_cvec[H];
__device__ __align__(16) float g_scale_h[H];
__device__ __align__(16) float g_shift_h[H];
__device__ __align__(16) float g_scale_e[H];
__device__ __align__(16) float g_shift_e[H];
__device__ __align__(16) unsigned char g_Bimg[6 * 65536];

// ---- smem layout ----
#define SM_SC    2048
#define SM_SH    2560
#define SM_A     4096
#define SM_C     4096
#define CSTRIDE  132
#define SM_STAGE 71680
#define SM_B     137216
#define SMEM_BYTES 202752

// ---- helpers ----
__device__ __forceinline__ uint32_t smem_u32(const void* p) {
    uint32_t a;
    asm("{ .reg .u64 t; cvta.to.shared.u64 t, %1; cvt.u32.u64 %0, t; }" : "=r"(a) : "l"(p));
    return a;
}
__device__ __forceinline__ uint32_t bpack(float a, float b) {
    __nv_bfloat162 t = __floats2bfloat162_rn(a, b);
    return *reinterpret_cast<uint32_t*>(&t);
}
__device__ __forceinline__ float bres(float a) {
    __nv_bfloat16 hh = __float2bfloat16_rn(a);
    return a - __bfloat162float(hh);
}
__device__ __forceinline__ void storeA8(char* hiP, char* loP, uint32_t off, const float* v) {
    uint4 hv, lv;
    hv.x = bpack(v[0], v[1]); hv.y = bpack(v[2], v[3]);
    hv.z = bpack(v[4], v[5]); hv.w = bpack(v[6], v[7]);
    lv.x = bpack(bres(v[0]), bres(v[1])); lv.y = bpack(bres(v[2]), bres(v[3]));
    lv.z = bpack(bres(v[4]), bres(v[5])); lv.w = bpack(bres(v[6]), bres(v[7]));
    *(uint4*)(hiP + off) = hv;
    *(uint4*)(loP + off) = lv;
}
__device__ __forceinline__ void ldsm4(uint32_t r[4], uint32_t addr) {
    asm volatile("ldmatrix.sync.aligned.m8n8.x4.shared.b16 {%0,%1,%2,%3}, [%4];"
        : "=r"(r[0]), "=r"(r[1]), "=r"(r[2]), "=r"(r[3]) : "r"(addr));
}
__device__ __forceinline__ void mma16816(float c[4], const uint32_t a[4], uint32_t b0, uint32_t b1) {
    asm volatile("mma.sync.aligned.m16n8k16.row.col.f32.bf16.bf16.f32 "
        "{%0,%1,%2,%3},{%4,%5,%6,%7},{%8,%9},{%0,%1,%2,%3};"
        : "+f"(c[0]), "+f"(c[1]), "+f"(c[2]), "+f"(c[3])
        : "r"(a[0]), "r"(a[1]), "r"(a[2]), "r"(a[3]), "r"(b0), "r"(b1));
}
__device__ __forceinline__ void redv4(float* p, float a, float b, float c, float d) {
    asm volatile("red.global.add.v4.f32 [%0], {%1, %2, %3, %4};"
        :: "l"(p), "f"(a), "f"(b), "f"(c), "f"(d) : "memory");
}
__device__ __forceinline__ void pf_l2(const void* p) {
    asm volatile("prefetch.global.L2 [%0];" :: "l"(p));
}
__device__ __forceinline__ void cpa16(uint32_t dst, const void* src, int pred) {
    asm volatile("{ .reg .pred p; setp.ne.b32 p, %2, 0;\n\t"
        "@p cp.async.cg.shared.global [%0], [%1], 16; }"
        :: "r"(dst), "l"(src), "r"(pred));
}
#define CP_COMMIT() asm volatile("cp.async.commit_group;" ::: "memory")
#define CP_WAIT0()  asm volatile("cp.async.wait_group 0;" ::: "memory")

// ---- GEMM core ----
__device__ __forceinline__ void gemm_compute(uint32_t sAu, uint32_t sBu, float C[8][4]) {
    int tid = threadIdx.x, lane = tid & 31, wid = tid >> 5;
    int rm = (wid & 7) * 16, cn = (wid >> 3) * 64;
#pragma unroll
    for (int nf = 0; nf < 8; nf++)
#pragma unroll
        for (int q = 0; q < 4; q++) C[nf][q] = 0.f;

    int xr = lane & 7;
    int arow = xr + ((lane >> 3) & 1) * 8;
    int ahs = lane >> 4;
    int bhs = (lane >> 3) & 1;
    int bnr = xr + (lane >> 4) * 8;
    uint32_t aB = sAu + (uint32_t)(rm + arow) * 256;
    uint32_t bB[4];
#pragma unroll
    for (int g = 0; g < 4; g++) bB[g] = sBu + (uint32_t)(cn + g * 16 + bnr) * 256;

#pragma unroll
    for (int ks = 0; ks < 8; ks++) {
        uint32_t oA = (uint32_t)(((ks * 2 + ahs) ^ xr) << 4);
        uint32_t oB = (uint32_t)(((ks * 2 + bhs) ^ xr) << 4);
        uint32_t aH[4], aL[4];
        ldsm4(aH, aB + oA);
        ldsm4(aL, aB + 32768 + oA);
        uint32_t bH[4][4], bL[4][4];
#pragma unroll
        for (int g = 0; g < 4; g++) {
            ldsm4(bH[g], bB[g] + oB);
            ldsm4(bL[g], bB[g] + 32768 + oB);
        }
#pragma unroll
        for (int g = 0; g < 4; g++) {
            mma16816(C[2*g],   aH, bH[g][0], bH[g][1]);
            mma16816(C[2*g+1], aH, bH[g][2], bH[g][3]);
            mma16816(C[2*g],   aH, bL[g][0], bL[g][1]);
            mma16816(C[2*g+1], aH, bL[g][2], bL[g][3]);
            mma16816(C[2*g],   aL, bH[g][0], bH[g][1]);
            mma16816(C[2*g+1], aL, bH[g][2], bH[g][3]);
        }
    }
}

__device__ __forceinline__ void gemm_storeC(float* Cs, float C[8][4]) {
    int tid = threadIdx.x, lane = tid & 31, wid = tid >> 5;
    int rm = (wid & 7) * 16, cn = (wid >> 3) * 64;
    int r = lane >> 2, c2 = 2 * (lane & 3);
#pragma unroll
    for (int nf = 0; nf < 8; nf++) {
        int col = cn + nf * 8 + c2;
        *(float2*)(Cs + (rm + r) * CSTRIDE + col)     = make_float2(C[nf][0], C[nf][1]);
        *(float2*)(Cs + (rm + r + 8) * CSTRIDE + col) = make_float2(C[nf][2], C[nf][3]);
    }
}

// ---- pipeline pieces ----
__device__ __forceinline__ void stage_A(uint32_t sb, const float* src, int r0, int limit) {
    int tid = threadIdx.x;
    uint32_t dst = sb + SM_STAGE;
#pragma unroll
    for (int it = 0; it < 8; it++) {
        int c = it * NT + tid;
        int row = c >> 5, part = c & 31;
        cpa16(dst + c * 16, src + (size_t)(r0 + row) * H + part * 4, (r0 + row) < limit);
    }
    CP_COMMIT();
}

__device__ __forceinline__ void convert_plain(char* sm) {
    const float* stg = (const float*)(sm + SM_STAGE);
    char* sA = sm + SM_A;
    int tid = threadIdx.x;
#pragma unroll
    for (int it = 0; it < 4; it++) {
        int s = it * NT + tid;
        int row = s >> 4, kseg = s & 15;
        const float4* p = (const float4*)(stg + row * 128 + kseg * 8);
        float4 f0 = p[0], f1 = p[1];
        float v[8] = {f0.x, f0.y, f0.z, f0.w, f1.x, f1.y, f1.z, f1.w};
        uint32_t off = (uint32_t)row * 256 + (uint32_t)((kseg ^ (row & 7)) << 4);
        storeA8(sA, sA + 32768, off, v);
    }
}

__device__ __forceinline__ void convert_bn(char* sm) {
    const float* stg = (const float*)(sm + SM_STAGE);
    const float4* sc4 = (const float4*)(sm + SM_SC);
    const float4* sh4 = (const float4*)(sm + SM_SH);
    char* sA = sm + SM_A;
    int tid = threadIdx.x;
#pragma unroll
    for (int it = 0; it < 4; it++) {
        int s = it * NT + tid;
        int row = s >> 4, kseg = s & 15;
        const float4* p = (const float4*)(stg + row * 128 + kseg * 8);
        float4 f0 = p[0], f1 = p[1];
        float4 s0 = sc4[kseg * 2], s1 = sc4[kseg * 2 + 1];
        float4 t0 = sh4[kseg * 2], t1 = sh4[kseg * 2 + 1];
        float v[8];
        v[0] = fmaxf(fmaf(f0.x, s0.x, t0.x), 0.f);
        v[1] = fmaxf(fmaf(f0.y, s0.y, t0.y), 0.f);
        v[2] = fmaxf(fmaf(f0.z, s0.z, t0.z), 0.f);
        v[3] = fmaxf(fmaf(f0.w, s0.w, t0.w), 0.f);
        v[4] = fmaxf(fmaf(f1.x, s1.x, t1.x), 0.f);
        v[5] = fmaxf(fmaf(f1.y, s1.y, t1.y), 0.f);
        v[6] = fmaxf(fmaf(f1.z, s1.z, t1.z), 0.f);
        v[7] = fmaxf(fmaf(f1.w, s1.w, t1.w), 0.f);
        uint32_t off = (uint32_t)row * 256 + (uint32_t)((kseg ^ (row & 7)) << 4);
        storeA8(sA, sA + 32768, off, v);
    }
}

__device__ __forceinline__ void copy_B(int widx, char* sB) {
    const uint4* g = (const uint4*)(g_Bimg + (size_t)widx * 65536);
    uint4* d = (uint4*)sB;
    int tid = threadIdx.x;
#pragma unroll
    for (int it = 0; it < 8; it++) d[it * NT + tid] = g[it * NT + tid];
}

__device__ __forceinline__ void load_idx(char* sm, const int* eidx, int t, int E, int p) {
    int tid = threadIdx.x;
    int e0 = t * 128;
    if (tid < 128) {
        int ei = e0 + tid;
        ((int*)(sm + p * 1024))[tid] = (ei < E) ? eidx[ei] : 0;
    } else if (tid < 256) {
        int q = tid - 128, ei = e0 + q;
        ((int*)(sm + p * 1024 + 512))[q] = (ei < E) ? eidx[(size_t)E + ei] : 0;
    }
}

__device__ __forceinline__ void prefetch_gathers(char* sm, int p) {
    const int* rI = (const int*)(sm + p * 1024);
    const int* cI = (const int*)(sm + p * 1024 + 512);
    int tid = threadIdx.x;
#pragma unroll
    for (int i = tid; i < 1536; i += NT) {
        int m = i & 127, sel = i >> 7;  // 0..11
        const float* ptr;
        if (sel < 8) ptr = g_colpack + (size_t)cI[m] * 256 + sel * 32;        // Vn|Ah full row
        else         ptr = g_rowpack + (size_t)rI[m] * 256 + (sel - 8) * 32;  // Bh half
        pf_l2(ptr);
    }
}

// ---------------------------------------------------------------------------
__global__ void k_init(const float* __restrict__ time_emb,
                       const float* __restrict__ Wt, const float* __restrict__ bt,
                       const float* __restrict__ Wo, const float* __restrict__ bo) {
    int j = threadIdx.x;
    for (int i = j; i < 4 * H; i += H) g_stats[i] = 0.0f;
    __shared__ float tv[H];
    float acc = bt[j];
    for (int k = 0; k < H; k++) acc += time_emb[k] * Wt[k * H + j];
    tv[j] = acc;
    __syncthreads();
    float c = bo[j];
    for (int k = 0; k < H; k++) c += tv[k] * Wo[k * H + j];
    g_cvec[j] = c;
}

// ---------------------------------------------------------------------------
__global__ void k_prep(const float* __restrict__ WU, const float* __restrict__ WV,
                       const float* __restrict__ WA, const float* __restrict__ WB,
                       const float* __restrict__ WC, const float* __restrict__ Wo) {
    const float* Ws[6] = {WU, WV, WA, WB, WC, Wo};
    const float* W = Ws[blockIdx.x];
    unsigned char* img = g_Bimg + (size_t)blockIdx.x * 65536;
    int tid = threadIdx.x;
    for (int it = 0; it < 64; it++) {
        int idx = it * 256 + tid;
        int k = idx >> 7, n = idx & 127;
        float v = W[k * H + n];
        __nv_bfloat16 hi = __float2bfloat16_rn(v);
        __nv_bfloat16 lo = __float2bfloat16_rn(v - __bfloat162float(hi));
        uint32_t off = (uint32_t)n * 256 + (uint32_t)((((k >> 3) ^ (n & 7))) << 4) + (k & 7) * 2;
        *(__nv_bfloat16*)(img + off) = hi;
        *(__nv_bfloat16*)(img + 32768 + off) = lo;
    }
}

// ---------------------------------------------------------------------------
// k_node (persistent per widx): writes into packed arrays (row stride 256)
// ---------------------------------------------------------------------------
__global__ __launch_bounds__(NT, 1) void k_node(
        const float* __restrict__ h,
        const float* __restrict__ bU, const float* __restrict__ bV,
        const float* __restrict__ bA, const float* __restrict__ bB,
        int V, int nTiles) {
    extern __shared__ char sm[];
    uint32_t sb = smem_u32(sm);
    int tid = threadIdx.x;
    int widx = blockIdx.y;

    copy_B(widx, sm + SM_B);
    float* out; const float* bias;
    switch (widx) {
        case 0:  out = g_rowpack + 128; bias = bU; break;  // agg (init Uh)
        case 1:  out = g_colpack;       bias = bV; break;  // Vn
        case 2:  out = g_colpack + 128; bias = bA; break;  // Ah
        default: out = g_rowpack;       bias = bB; break;  // Bh
    }

    int t = blockIdx.x;
    if (t >= nTiles) return;
    stage_A(sb, h, t * 128, V);
    CP_WAIT0(); __syncthreads();
    convert_plain(sm);
    __syncthreads();

    while (t < nTiles) {
        int nxt = t + gridDim.x;
        if (nxt < nTiles) stage_A(sb, h, nxt * 128, V);

        float C[8][4];
        gemm_compute(sb + SM_A, sb + SM_B, C);
        __syncthreads();
        gemm_storeC((float*)(sm + SM_C), C);
        __syncthreads();

        int r0 = t * 128;
        const float* Cs = (const float*)(sm + SM_C);
#pragma unroll
        for (int it = 0; it < 8; it++) {
            int idx = it * NT + tid;
            int row = idx >> 5, cs = idx & 31;
            if (r0 + row < V) {
                float4 c = *(const float4*)(Cs + row * CSTRIDE + cs * 4);
                float4 b = *(const float4*)(bias + cs * 4);
                c.x += b.x; c.y += b.y; c.z += b.z; c.w += b.w;
                *(float4*)(out + (size_t)(r0 + row) * 256 + cs * 4) = c;
            }
        }
        CP_WAIT0();
        __syncthreads();
        if (nxt < nTiles) convert_plain(sm);
        __syncthreads();
        t = nxt;
    }
}

// ---------------------------------------------------------------------------
// k_edge (persistent): packed gathers + red.v4 scatter
// ---------------------------------------------------------------------------
__global__ __launch_bounds__(NT, 1) void k_edge(
        const float* __restrict__ e, const float* __restrict__ bC,
        const int* __restrict__ eidx, int E, int nTiles) {
    extern __shared__ char sm[];
    uint32_t sb = smem_u32(sm);
    int tid = threadIdx.x, lane = tid & 31, w = tid >> 5;

    copy_B(4, sm + SM_B);
    float4 bc = *(const float4*)(bC + lane * 4);
    float ss[4] = {0.f, 0.f, 0.f, 0.f}, sq[4] = {0.f, 0.f, 0.f, 0.f};

    int t = blockIdx.x, p = 0;
    if (t < nTiles) {
        load_idx(sm, eidx, t, E, 0);
        stage_A(sb, e, t * 128, E);
        CP_WAIT0(); __syncthreads();
        convert_plain(sm);
        prefetch_gathers(sm, 0);
        __syncthreads();

        while (t < nTiles) {
            int nxt = t + gridDim.x;
            if (nxt < nTiles) {
                stage_A(sb, e, nxt * 128, E);
                load_idx(sm, eidx, nxt, E, p ^ 1);
            }

            float C[8][4];
            gemm_compute(sb + SM_A, sb + SM_B, C);
            __syncthreads();
            gemm_storeC((float*)(sm + SM_C), C);
            __syncthreads();

            int e0 = t * 128;
            const int* rI = (const int*)(sm + p * 1024);
            const int* cI = (const int*)(sm + p * 1024 + 512);
            const float* Cs = (const float*)(sm + SM_C);
#pragma unroll
            for (int k = 0; k < 8; k++) {
                int m = w * 8 + k;
                int ei = e0 + m;
                if (ei < E) {
                    const float* cp = g_colpack + (size_t)cI[m] * 256;
                    float* rp = g_rowpack + (size_t)rI[m] * 256;
                    float4 cc = *(const float4*)(Cs + m * CSTRIDE + lane * 4);
                    float4 vn = *(const float4*)(cp + lane * 4);
                    float4 ah = *(const float4*)(cp + 128 + lane * 4);
                    float4 bh = *(const float4*)(rp + lane * 4);
                    float4 x;
                    x.x = cc.x + bc.x + ah.x + bh.x;
                    x.y = cc.y + bc.y + ah.y + bh.y;
                    x.z = cc.z + bc.z + ah.z + bh.z;
                    x.w = cc.w + bc.w + ah.w + bh.w;
                    *(float4*)(g_epre + (size_t)ei * H + lane * 4) = x;
                    float ga = vn.x / (1.f + __expf(-x.x));
                    float gb = vn.y / (1.f + __expf(-x.y));
                    float gc = vn.z / (1.f + __expf(-x.z));
                    float gd = vn.w / (1.f + __expf(-x.w));
                    redv4(rp + 128 + lane * 4, ga, gb, gc, gd);
                    ss[0] += x.x; ss[1] += x.y; ss[2] += x.z; ss[3] += x.w;
                    sq[0] += x.x * x.x; sq[1] += x.y * x.y;
                    sq[2] += x.z * x.z; sq[3] += x.w * x.w;
                }
            }
            if (nxt < nTiles) prefetch_gathers(sm, p ^ 1);
            CP_WAIT0();
            __syncthreads();
            if (nxt < nTiles) convert_plain(sm);
            __syncthreads();
            t = nxt; p ^= 1;
        }
    }

    float* sr = (float*)(sm + SM_STAGE);
    float* qr = sr + 2048;
    *(float4*)(sr + w * 128 + lane * 4) = make_float4(ss[0], ss[1], ss[2], ss[3]);
    *(float4*)(qr + w * 128 + lane * 4) = make_float4(sq[0], sq[1], sq[2], sq[3]);
    __syncthreads();
    if (tid < 128) {
        float a = 0.f, b = 0.f;
#pragma unroll
        for (int ww = 0; ww < 16; ww++) { a += sr[ww * 128 + tid]; b += qr[ww * 128 + tid]; }
        atomicAdd(&g_stats[2 * H + tid], a);
        atomicAdd(&g_stats[3 * H + tid], b);
    }
}

// ---------------------------------------------------------------------------
__global__ __launch_bounds__(NT, 1) void k_edgeout(
        const float* __restrict__ e, float* __restrict__ out, int E, int nTiles) {
    extern __shared__ char sm[];
    uint32_t sb = smem_u32(sm);
    int tid = threadIdx.x, lane = tid & 31, w = tid >> 5;

    copy_B(5, sm + SM_B);
    if (tid < 128) {
        ((float*)(sm + SM_SC))[tid] = g_scale_e[tid];
        ((float*)(sm + SM_SH))[tid] = g_shift_e[tid];
    }
    float4 cv4 = *(const float4*)(g_cvec + lane * 4);

    int t = blockIdx.x;
    if (t >= nTiles) return;

    stage_A(sb, g_epre, t * 128, E);
    CP_WAIT0(); __syncthreads();
    convert_bn(sm);
    __syncthreads();

    while (t < nTiles) {
        int nxt = t + gridDim.x;
        if (nxt < nTiles) stage_A(sb, g_epre, nxt * 128, E);

        float C[8][4];
        gemm_compute(sb + SM_A, sb + SM_B, C);
        __syncthreads();
        gemm_storeC((float*)(sm + SM_C), C);
        __syncthreads();

        int e0 = t * 128;
        const float* Cs = (const float*)(sm + SM_C);
#pragma unroll
        for (int k = 0; k < 8; k++) {
            int m = w * 8 + k;
            int ei = e0 + m;
            if (ei < E) {
                float4 cc = *(const float4*)(Cs + m * CSTRIDE + lane * 4);
                float4 ev = *(const float4*)(e + (size_t)ei * H + lane * 4);
                float4 o;
                o.x = ev.x + cc.x + cv4.x;
                o.y = ev.y + cc.y + cv4.y;
                o.z = ev.z + cc.z + cv4.z;
                o.w = ev.w + cc.w + cv4.w;
                *(float4*)(out + (size_t)ei * H + lane * 4) = o;
            }
        }
        CP_WAIT0();
        __syncthreads();
        if (nxt < nTiles) convert_bn(sm);
        __syncthreads();
        t = nxt;
    }
}

// ---------------------------------------------------------------------------
__global__ void k_nstats(int rows) {
    int tid = threadIdx.x;
    int cg = tid & 31, wr = tid >> 5;
    float4 s = make_float4(0.f, 0.f, 0.f, 0.f);
    float4 qq = make_float4(0.f, 0.f, 0.f, 0.f);
    const float4* s4 = (const float4*)g_rowpack;
    for (int r = blockIdx.x * 8 + wr; r < rows; r += gridDim.x * 8) {
        float4 x = s4[(size_t)r * 64 + 32 + cg];  // agg half of rowpack
        s.x += x.x; s.y += x.y; s.z += x.z; s.w += x.w;
        qq.x += x.x * x.x; qq.y += x.y * x.y; qq.z += x.z * x.z; qq.w += x.w * x.w;
    }
    __shared__ float sh1[8][128], sh2[8][128];
    *(float4*)&sh1[wr][cg * 4] = s;
    *(float4*)&sh2[wr][cg * 4] = qq;
    __syncthreads();
    if (tid < 128) {
        float a = 0.f, b = 0.f;
#pragma unroll
        for (int ww = 0; ww < 8; ww++) { a += sh1[ww][tid]; b += sh2[ww][tid]; }
        atomicAdd(&g_stats[tid], a);
        atomicAdd(&g_stats[H + tid], b);
    }
}

// ---------------------------------------------------------------------------
__global__ void k_finalize(const float* __restrict__ gh, const float* __restrict__ bh,
                           const float* __restrict__ ge, const float* __restrict__ be,
                           int V, int E) {
    int j = threadIdx.x;
    float invV = 1.0f / (float)V, invE = 1.0f / (float)E;
    float mh = g_stats[j] * invV;
    float vh = g_stats[H + j] * invV - mh * mh;
    float sc = gh[j] * rsqrtf(vh + 1e-5f);
    g_scale_h[j] = sc;
    g_shift_h[j] = bh[j] - mh * sc;
    float me = g_stats[2 * H + j] * invE;
    float ve = g_stats[3 * H + j] * invE - me * me;
    float se = ge[j] * rsqrtf(ve + 1e-5f);
    g_scale_e[j] = se;
    g_shift_e[j] = be[j] - me * se;
}

// ---------------------------------------------------------------------------
__global__ void k_nodeout(const float* __restrict__ h, float* __restrict__ out, int V) {
    int idx = blockIdx.x * blockDim.x + threadIdx.x;
    int total = V * (H / 4);
    if (idx >= total) return;
    int row = idx >> 5, cs = idx & 31;
    int j = cs * 4;
    float4 a  = *(const float4*)&g_rowpack[(size_t)row * 256 + 128 + j];
    float4 sc = *(const float4*)&g_scale_h[j];
    float4 sh = *(const float4*)&g_shift_h[j];
    float4 hv = *(const float4*)&h[(size_t)idx * 4];
    float4 r;
    r.x = hv.x + fmaxf(fmaf(a.x, sc.x, sh.x), 0.f);
    r.y = hv.y + fmaxf(fmaf(a.y, sc.y, sh.y), 0.f);
    r.z = hv.z + fmaxf(fmaf(a.z, sc.z, sh.z), 0.f);
    r.w = hv.w + fmaxf(fmaf(a.w, sc.w, sh.w), 0.f);
    *(float4*)&out[(size_t)idx * 4] = r;
}

// ---------------------------------------------------------------------------
extern "C" void kernel_launch(void* const* d_in, const int* in_sizes, int n_in,
                              void* d_out, int out_size) {
    const float* h        = (const float*)d_in[0];
    const float* e        = (const float*)d_in[1];
    const float* time_emb = (const float*)d_in[2];
    const int*   eidx     = (const int*)d_in[3];
    const float* WU = (const float*)d_in[4];  const float* bU = (const float*)d_in[5];
    const float* WV = (const float*)d_in[6];  const float* bV = (const float*)d_in[7];
    const float* WA = (const float*)d_in[8];  const float* bA = (const float*)d_in[9];
    const float* WB = (const float*)d_in[10]; const float* bB = (const float*)d_in[11];
    const float* WC = (const float*)d_in[12]; const float* bC = (const float*)d_in[13];
    const float* Wt = (const float*)d_in[14]; const float* bt = (const float*)d_in[15];
    const float* Wo = (const float*)d_in[16]; const float* bo = (const float*)d_in[17];
    const float* gh = (const float*)d_in[18]; const float* bh = (const float*)d_in[19];
    const float* ge = (const float*)d_in[20]; const float* be = (const float*)d_in[21];

    int V = in_sizes[0] / H;
    int E = in_sizes[3] / 2;

    float* xout = (float*)d_out;
    float* eout = xout + (size_t)V * H;

    cudaFuncSetAttribute(k_node,    cudaFuncAttributeMaxDynamicSharedMemorySize, SMEM_BYTES);
    cudaFuncSetAttribute(k_edge,    cudaFuncAttributeMaxDynamicSharedMemorySize, SMEM_BYTES);
    cudaFuncSetAttribute(k_edgeout, cudaFuncAttributeMaxDynamicSharedMemorySize, SMEM_BYTES);

    int vTiles = (V + 127) / 128;
    int eTiles = (E + 127) / 128;
    int gxNode = vTiles < 37 ? vTiles : 37;
    int gxEdge = eTiles < 148 ? eTiles : 148;

    k_init<<<1, 128>>>(time_emb, Wt, bt, Wo, bo);
    k_prep<<<6, 256>>>(WU, WV, WA, WB, WC, Wo);
    k_node<<<dim3(gxNode, 4), NT, SMEM_BYTES>>>(h, bU, bV, bA, bB, V, vTiles);
    k_edge<<<gxEdge, NT, SMEM_BYTES>>>(e, bC, eidx, E, eTiles);
    k_nstats<<<512, 256>>>(V);
    k_finalize<<<1, 128>>>(gh, bh, ge, be, V, E);
    k_nodeout<<<(V * (H / 4) + 255) / 256, 256>>>(h, xout, V);
    k_edgeout<<<gxEdge, NT, SMEM_BYTES>>>(e, eout, E, eTiles);
}

// round 8
// speedup vs baseline: 2.5038x; 1.0094x over previous
#include <cuda_runtime.h>
#include <cuda_bf16.h>
#include <cstdint>

// ---------------------------------------------------------------------------
// DAGCondGNNEncoder (sm_103 HMMA path): split-bf16 mma.sync GEMMs.
// R8: direct fragment epilogues (k_node/k_edgeout, no SMEM C round-trip,
//     2 syncs/iter), software-pipelined gather epilogue in k_edge,
//     L2 prefetch of e-tile in k_edgeout.
// ---------------------------------------------------------------------------

#define H 128
#define VMAX 50000
#define EMAX 625000
#define NT 512

// ---- device scratch ----
__device__ __align__(16) float g_colpack[(size_t)VMAX * 256];  // [Vn | Ah]
__device__ __align__(16) float g_rowpack[(size_t)VMAX * 256];  // [Bh | agg]
__device__ __align__(16) float g_epre[(size_t)EMAX * H];
__device__ __align__(16) float g_stats[4 * H];
__device__ __align__(16) float g_cvec[H];
__device__ __align__(16) float g_scale_h[H];
__device__ __align__(16) float g_shift_h[H];
__device__ __align__(16) float g_scale_e[H];
__device__ __align__(16) float g_shift_e[H];
__device__ __align__(16) unsigned char g_Bimg[6 * 65536];

// ---- smem layout ----
#define SM_SC    2048
#define SM_SH    2560
#define SM_A     4096
#define SM_C     4096
#define CSTRIDE  132
#define SM_STAGE 71680
#define SM_B     137216
#define SMEM_BYTES 202752

// ---- helpers ----
__device__ __forceinline__ uint32_t smem_u32(const void* p) {
    uint32_t a;
    asm("{ .reg .u64 t; cvta.to.shared.u64 t, %1; cvt.u32.u64 %0, t; }" : "=r"(a) : "l"(p));
    return a;
}
__device__ __forceinline__ uint32_t bpack(float a, float b) {
    __nv_bfloat162 t = __floats2bfloat162_rn(a, b);
    return *reinterpret_cast<uint32_t*>(&t);
}
__device__ __forceinline__ float bres(float a) {
    __nv_bfloat16 hh = __float2bfloat16_rn(a);
    return a - __bfloat162float(hh);
}
__device__ __forceinline__ void storeA8(char* hiP, char* loP, uint32_t off, const float* v) {
    uint4 hv, lv;
    hv.x = bpack(v[0], v[1]); hv.y = bpack(v[2], v[3]);
    hv.z = bpack(v[4], v[5]); hv.w = bpack(v[6], v[7]);
    lv.x = bpack(bres(v[0]), bres(v[1])); lv.y = bpack(bres(v[2]), bres(v[3]));
    lv.z = bpack(bres(v[4]), bres(v[5])); lv.w = bpack(bres(v[6]), bres(v[7]));
    *(uint4*)(hiP + off) = hv;
    *(uint4*)(loP + off) = lv;
}
__device__ __forceinline__ void ldsm4(uint32_t r[4], uint32_t addr) {
    asm volatile("ldmatrix.sync.aligned.m8n8.x4.shared.b16 {%0,%1,%2,%3}, [%4];"
        : "=r"(r[0]), "=r"(r[1]), "=r"(r[2]), "=r"(r[3]) : "r"(addr));
}
__device__ __forceinline__ void mma16816(float c[4], const uint32_t a[4], uint32_t b0, uint32_t b1) {
    asm volatile("mma.sync.aligned.m16n8k16.row.col.f32.bf16.bf16.f32 "
        "{%0,%1,%2,%3},{%4,%5,%6,%7},{%8,%9},{%0,%1,%2,%3};"
        : "+f"(c[0]), "+f"(c[1]), "+f"(c[2]), "+f"(c[3])
        : "r"(a[0]), "r"(a[1]), "r"(a[2]), "r"(a[3]), "r"(b0), "r"(b1));
}
__device__ __forceinline__ void redv4(float* p, float a, float b, float c, float d) {
    asm volatile("red.global.add.v4.f32 [%0], {%1, %2, %3, %4};"
        :: "l"(p), "f"(a), "f"(b), "f"(c), "f"(d) : "memory");
}
__device__ __forceinline__ void pf_l2(const void* p) {
    asm volatile("prefetch.global.L2 [%0];" :: "l"(p));
}
__device__ __forceinline__ void cpa16(uint32_t dst, const void* src, int pred) {
    asm volatile("{ .reg .pred p; setp.ne.b32 p, %2, 0;\n\t"
        "@p cp.async.cg.shared.global [%0], [%1], 16; }"
        :: "r"(dst), "l"(src), "r"(pred));
}
#define CP_COMMIT() asm volatile("cp.async.commit_group;" ::: "memory")
#define CP_WAIT0()  asm volatile("cp.async.wait_group 0;" ::: "memory")

// ---- GEMM core: 128x128x128 tile, 16 warps, warp tile 16x64 ----
__device__ __forceinline__ void gemm_compute(uint32_t sAu, uint32_t sBu, float C[8][4]) {
    int tid = threadIdx.x, lane = tid & 31, wid = tid >> 5;
    int rm = (wid & 7) * 16, cn = (wid >> 3) * 64;
#pragma unroll
    for (int nf = 0; nf < 8; nf++)
#pragma unroll
        for (int q = 0; q < 4; q++) C[nf][q] = 0.f;

    int xr = lane & 7;
    int arow = xr + ((lane >> 3) & 1) * 8;
    int ahs = lane >> 4;
    int bhs = (lane >> 3) & 1;
    int bnr = xr + (lane >> 4) * 8;
    uint32_t aB = sAu + (uint32_t)(rm + arow) * 256;
    uint32_t bB[4];
#pragma unroll
    for (int g = 0; g < 4; g++) bB[g] = sBu + (uint32_t)(cn + g * 16 + bnr) * 256;

#pragma unroll
    for (int ks = 0; ks < 8; ks++) {
        uint32_t oA = (uint32_t)(((ks * 2 + ahs) ^ xr) << 4);
        uint32_t oB = (uint32_t)(((ks * 2 + bhs) ^ xr) << 4);
        uint32_t aH[4], aL[4];
        ldsm4(aH, aB + oA);
        ldsm4(aL, aB + 32768 + oA);
        uint32_t bH[4][4], bL[4][4];
#pragma unroll
        for (int g = 0; g < 4; g++) {
            ldsm4(bH[g], bB[g] + oB);
            ldsm4(bL[g], bB[g] + 32768 + oB);
        }
#pragma unroll
        for (int g = 0; g < 4; g++) {
            mma16816(C[2*g],   aH, bH[g][0], bH[g][1]);
            mma16816(C[2*g+1], aH, bH[g][2], bH[g][3]);
            mma16816(C[2*g],   aH, bL[g][0], bL[g][1]);
            mma16816(C[2*g+1], aH, bL[g][2], bL[g][3]);
            mma16816(C[2*g],   aL, bH[g][0], bH[g][1]);
            mma16816(C[2*g+1], aL, bH[g][2], bH[g][3]);
        }
    }
}

__device__ __forceinline__ void gemm_storeC(float* Cs, float C[8][4]) {
    int tid = threadIdx.x, lane = tid & 31, wid = tid >> 5;
    int rm = (wid & 7) * 16, cn = (wid >> 3) * 64;
    int r = lane >> 2, c2 = 2 * (lane & 3);
#pragma unroll
    for (int nf = 0; nf < 8; nf++) {
        int col = cn + nf * 8 + c2;
        *(float2*)(Cs + (rm + r) * CSTRIDE + col)     = make_float2(C[nf][0], C[nf][1]);
        *(float2*)(Cs + (rm + r + 8) * CSTRIDE + col) = make_float2(C[nf][2], C[nf][3]);
    }
}

// ---- pipeline pieces ----
__device__ __forceinline__ void stage_A(uint32_t sb, const float* src, int r0, int limit) {
    int tid = threadIdx.x;
    uint32_t dst = sb + SM_STAGE;
#pragma unroll
    for (int it = 0; it < 8; it++) {
        int c = it * NT + tid;
        int row = c >> 5, part = c & 31;
        cpa16(dst + c * 16, src + (size_t)(r0 + row) * H + part * 4, (r0 + row) < limit);
    }
    CP_COMMIT();
}

__device__ __forceinline__ void convert_plain(char* sm) {
    const float* stg = (const float*)(sm + SM_STAGE);
    char* sA = sm + SM_A;
    int tid = threadIdx.x;
#pragma unroll
    for (int it = 0; it < 4; it++) {
        int s = it * NT + tid;
        int row = s >> 4, kseg = s & 15;
        const float4* p = (const float4*)(stg + row * 128 + kseg * 8);
        float4 f0 = p[0], f1 = p[1];
        float v[8] = {f0.x, f0.y, f0.z, f0.w, f1.x, f1.y, f1.z, f1.w};
        uint32_t off = (uint32_t)row * 256 + (uint32_t)((kseg ^ (row & 7)) << 4);
        storeA8(sA, sA + 32768, off, v);
    }
}

__device__ __forceinline__ void convert_bn(char* sm) {
    const float* stg = (const float*)(sm + SM_STAGE);
    const float4* sc4 = (const float4*)(sm + SM_SC);
    const float4* sh4 = (const float4*)(sm + SM_SH);
    char* sA = sm + SM_A;
    int tid = threadIdx.x;
#pragma unroll
    for (int it = 0; it < 4; it++) {
        int s = it * NT + tid;
        int row = s >> 4, kseg = s & 15;
        const float4* p = (const float4*)(stg + row * 128 + kseg * 8);
        float4 f0 = p[0], f1 = p[1];
        float4 s0 = sc4[kseg * 2], s1 = sc4[kseg * 2 + 1];
        float4 t0 = sh4[kseg * 2], t1 = sh4[kseg * 2 + 1];
        float v[8];
        v[0] = fmaxf(fmaf(f0.x, s0.x, t0.x), 0.f);
        v[1] = fmaxf(fmaf(f0.y, s0.y, t0.y), 0.f);
        v[2] = fmaxf(fmaf(f0.z, s0.z, t0.z), 0.f);
        v[3] = fmaxf(fmaf(f0.w, s0.w, t0.w), 0.f);
        v[4] = fmaxf(fmaf(f1.x, s1.x, t1.x), 0.f);
        v[5] = fmaxf(fmaf(f1.y, s1.y, t1.y), 0.f);
        v[6] = fmaxf(fmaf(f1.z, s1.z, t1.z), 0.f);
        v[7] = fmaxf(fmaf(f1.w, s1.w, t1.w), 0.f);
        uint32_t off = (uint32_t)row * 256 + (uint32_t)((kseg ^ (row & 7)) << 4);
        storeA8(sA, sA + 32768, off, v);
    }
}

__device__ __forceinline__ void copy_B(int widx, char* sB) {
    const uint4* g = (const uint4*)(g_Bimg + (size_t)widx * 65536);
    uint4* d = (uint4*)sB;
    int tid = threadIdx.x;
#pragma unroll
    for (int it = 0; it < 8; it++) d[it * NT + tid] = g[it * NT + tid];
}

__device__ __forceinline__ void load_idx(char* sm, const int* eidx, int t, int E, int p) {
    int tid = threadIdx.x;
    int e0 = t * 128;
    if (tid < 128) {
        int ei = e0 + tid;
        ((int*)(sm + p * 1024))[tid] = (ei < E) ? eidx[ei] : 0;
    } else if (tid < 256) {
        int q = tid - 128, ei = e0 + q;
        ((int*)(sm + p * 1024 + 512))[q] = (ei < E) ? eidx[(size_t)E + ei] : 0;
    }
}

__device__ __forceinline__ void prefetch_gathers(char* sm, int p) {
    const int* rI = (const int*)(sm + p * 1024);
    const int* cI = (const int*)(sm + p * 1024 + 512);
    int tid = threadIdx.x;
#pragma unroll
    for (int i = tid; i < 1536; i += NT) {
        int m = i & 127, sel = i >> 7;
        const float* ptr;
        if (sel < 8) ptr = g_colpack + (size_t)cI[m] * 256 + sel * 32;
        else         ptr = g_rowpack + (size_t)rI[m] * 256 + (sel - 8) * 32;
        pf_l2(ptr);
    }
}

// ---------------------------------------------------------------------------
__global__ void k_init(const float* __restrict__ time_emb,
                       const float* __restrict__ Wt, const float* __restrict__ bt,
                       const float* __restrict__ Wo, const float* __restrict__ bo) {
    int j = threadIdx.x;
    for (int i = j; i < 4 * H; i += H) g_stats[i] = 0.0f;
    __shared__ float tv[H];
    float acc = bt[j];
    for (int k = 0; k < H; k++) acc += time_emb[k] * Wt[k * H + j];
    tv[j] = acc;
    __syncthreads();
    float c = bo[j];
    for (int k = 0; k < H; k++) c += tv[k] * Wo[k * H + j];
    g_cvec[j] = c;
}

// ---------------------------------------------------------------------------
__global__ void k_prep(const float* __restrict__ WU, const float* __restrict__ WV,
                       const float* __restrict__ WA, const float* __restrict__ WB,
                       const float* __restrict__ WC, const float* __restrict__ Wo) {
    const float* Ws[6] = {WU, WV, WA, WB, WC, Wo};
    const float* W = Ws[blockIdx.x];
    unsigned char* img = g_Bimg + (size_t)blockIdx.x * 65536;
    int tid = threadIdx.x;
    for (int it = 0; it < 64; it++) {
        int idx = it * 256 + tid;
        int k = idx >> 7, n = idx & 127;
        float v = W[k * H + n];
        __nv_bfloat16 hi = __float2bfloat16_rn(v);
        __nv_bfloat16 lo = __float2bfloat16_rn(v - __bfloat162float(hi));
        uint32_t off = (uint32_t)n * 256 + (uint32_t)((((k >> 3) ^ (n & 7))) << 4) + (k & 7) * 2;
        *(__nv_bfloat16*)(img + off) = hi;
        *(__nv_bfloat16*)(img + 32768 + off) = lo;
    }
}

// ---------------------------------------------------------------------------
// k_node: persistent, direct fragment epilogue (no SMEM C), 2 syncs/iter
// ---------------------------------------------------------------------------
__global__ __launch_bounds__(NT, 1) void k_node(
        const float* __restrict__ h,
        const float* __restrict__ bU, const float* __restrict__ bV,
        const float* __restrict__ bA, const float* __restrict__ bB,
        int V, int nTiles) {
    extern __shared__ char sm[];
    uint32_t sb = smem_u32(sm);
    int tid = threadIdx.x, lane = tid & 31, wid = tid >> 5;
    int rm = (wid & 7) * 16, cn = (wid >> 3) * 64;
    int r_in = lane >> 2, c2 = 2 * (lane & 3);
    int widx = blockIdx.y;

    copy_B(widx, sm + SM_B);
    float* out; const float* bias;
    switch (widx) {
        case 0:  out = g_rowpack + 128; bias = bU; break;
        case 1:  out = g_colpack;       bias = bV; break;
        case 2:  out = g_colpack + 128; bias = bA; break;
        default: out = g_rowpack;       bias = bB; break;
    }
    float2 bv[8];
#pragma unroll
    for (int nf = 0; nf < 8; nf++) bv[nf] = *(const float2*)(bias + cn + nf * 8 + c2);

    int t = blockIdx.x;
    if (t >= nTiles) return;
    stage_A(sb, h, t * 128, V);
    CP_WAIT0(); __syncthreads();
    convert_plain(sm);
    __syncthreads();

    while (t < nTiles) {
        int nxt = t + gridDim.x;
        if (nxt < nTiles) stage_A(sb, h, nxt * 128, V);

        float C[8][4];
        gemm_compute(sb + SM_A, sb + SM_B, C);

        int r0 = t * 128;
#pragma unroll
        for (int nf = 0; nf < 8; nf++) {
#pragma unroll
            for (int hf = 0; hf < 2; hf++) {
                int row = r0 + rm + hf * 8 + r_in;
                if (row < V) {
                    float2 o = make_float2(C[nf][2 * hf] + bv[nf].x,
                                           C[nf][2 * hf + 1] + bv[nf].y);
                    *(float2*)(out + (size_t)row * 256 + cn + nf * 8 + c2) = o;
                }
            }
        }
        CP_WAIT0();
        __syncthreads();
        if (nxt < nTiles) convert_plain(sm);
        __syncthreads();
        t = nxt;
    }
}

// ---------------------------------------------------------------------------
// k_edge: persistent; SMEM C path (stats need row-major lanes); pipelined
//         gather epilogue.
// ---------------------------------------------------------------------------
__global__ __launch_bounds__(NT, 1) void k_edge(
        const float* __restrict__ e, const float* __restrict__ bC,
        const int* __restrict__ eidx, int E, int nTiles) {
    extern __shared__ char sm[];
    uint32_t sb = smem_u32(sm);
    int tid = threadIdx.x, lane = tid & 31, w = tid >> 5;

    copy_B(4, sm + SM_B);
    float4 bc = *(const float4*)(bC + lane * 4);
    float ss[4] = {0.f, 0.f, 0.f, 0.f}, sq[4] = {0.f, 0.f, 0.f, 0.f};

    int t = blockIdx.x, p = 0;
    if (t < nTiles) {
        load_idx(sm, eidx, t, E, 0);
        stage_A(sb, e, t * 128, E);
        CP_WAIT0(); __syncthreads();
        convert_plain(sm);
        prefetch_gathers(sm, 0);
        __syncthreads();

        while (t < nTiles) {
            int nxt = t + gridDim.x;
            if (nxt < nTiles) {
                stage_A(sb, e, nxt * 128, E);
                load_idx(sm, eidx, nxt, E, p ^ 1);
            }

            float C[8][4];
            gemm_compute(sb + SM_A, sb + SM_B, C);
            __syncthreads();
            gemm_storeC((float*)(sm + SM_C), C);
            __syncthreads();

            int e0 = t * 128;
            const int* rI = (const int*)(sm + p * 1024);
            const int* cI = (const int*)(sm + p * 1024 + 512);
            const float* Cs = (const float*)(sm + SM_C);
            int m0 = w * 8;

            // pipelined epilogue: prefetch row k+1 gathers during row k math
            float4 cc, vn, ah, bh;
            float* rp_cur;
            {
                int m = m0;
                int rv = rI[m], cv = cI[m];
                const float* cp = g_colpack + (size_t)cv * 256;
                rp_cur = g_rowpack + (size_t)rv * 256;
                cc = *(const float4*)(Cs + m * CSTRIDE + lane * 4);
                vn = *(const float4*)(cp + lane * 4);
                ah = *(const float4*)(cp + 128 + lane * 4);
                bh = *(const float4*)(rp_cur + lane * 4);
            }
#pragma unroll
            for (int k = 0; k < 8; k++) {
                int m = m0 + k;
                int ei = e0 + m;
                float4 ccn, vnn, ahn, bhn;
                float* rp_nxt = rp_cur;
                if (k < 7) {
                    int mn = m + 1;
                    int rv = rI[mn], cv = cI[mn];
                    const float* cp = g_colpack + (size_t)cv * 256;
                    rp_nxt = g_rowpack + (size_t)rv * 256;
                    ccn = *(const float4*)(Cs + mn * CSTRIDE + lane * 4);
                    vnn = *(const float4*)(cp + lane * 4);
                    ahn = *(const float4*)(cp + 128 + lane * 4);
                    bhn = *(const float4*)(rp_nxt + lane * 4);
                }
                if (ei < E) {
                    float4 x;
                    x.x = cc.x + bc.x + ah.x + bh.x;
                    x.y = cc.y + bc.y + ah.y + bh.y;
                    x.z = cc.z + bc.z + ah.z + bh.z;
                    x.w = cc.w + bc.w + ah.w + bh.w;
                    *(float4*)(g_epre + (size_t)ei * H + lane * 4) = x;
                    float ga = vn.x / (1.f + __expf(-x.x));
                    float gb = vn.y / (1.f + __expf(-x.y));
                    float gc = vn.z / (1.f + __expf(-x.z));
                    float gd = vn.w / (1.f + __expf(-x.w));
                    redv4(rp_cur + 128 + lane * 4, ga, gb, gc, gd);
                    ss[0] += x.x; ss[1] += x.y; ss[2] += x.z; ss[3] += x.w;
                    sq[0] += x.x * x.x; sq[1] += x.y * x.y;
                    sq[2] += x.z * x.z; sq[3] += x.w * x.w;
                }
                cc = ccn; vn = vnn; ah = ahn; bh = bhn; rp_cur = rp_nxt;
            }

            if (nxt < nTiles) prefetch_gathers(sm, p ^ 1);
            CP_WAIT0();
            __syncthreads();
            if (nxt < nTiles) convert_plain(sm);
            __syncthreads();
            t = nxt; p ^= 1;
        }
    }

    float* sr = (float*)(sm + SM_STAGE);
    float* qr = sr + 2048;
    *(float4*)(sr + w * 128 + lane * 4) = make_float4(ss[0], ss[1], ss[2], ss[3]);
    *(float4*)(qr + w * 128 + lane * 4) = make_float4(sq[0], sq[1], sq[2], sq[3]);
    __syncthreads();
    if (tid < 128) {
        float a = 0.f, b = 0.f;
#pragma unroll
        for (int ww = 0; ww < 16; ww++) { a += sr[ww * 128 + tid]; b += qr[ww * 128 + tid]; }
        atomicAdd(&g_stats[2 * H + tid], a);
        atomicAdd(&g_stats[3 * H + tid], b);
    }
}

// ---------------------------------------------------------------------------
// k_edgeout: persistent, direct fragment epilogue, pf_l2 of e-tile
// ---------------------------------------------------------------------------
__global__ __launch_bounds__(NT, 1) void k_edgeout(
        const float* __restrict__ e, float* __restrict__ out, int E, int nTiles) {
    extern __shared__ char sm[];
    uint32_t sb = smem_u32(sm);
    int tid = threadIdx.x, lane = tid & 31, wid = tid >> 5;
    int rm = (wid & 7) * 16, cn = (wid >> 3) * 64;
    int r_in = lane >> 2, c2 = 2 * (lane & 3);

    copy_B(5, sm + SM_B);
    if (tid < 128) {
        ((float*)(sm + SM_SC))[tid] = g_scale_e[tid];
        ((float*)(sm + SM_SH))[tid] = g_shift_e[tid];
    }
    float2 cv2[8];
#pragma unroll
    for (int nf = 0; nf < 8; nf++) cv2[nf] = *(const float2*)(g_cvec + cn + nf * 8 + c2);

    int t = blockIdx.x;
    if (t >= nTiles) return;

    stage_A(sb, g_epre, t * 128, E);
    // warm L2 with e rows of this tile
    {
        int row = tid >> 2, part = (tid & 3) * 32;
        if (t * 128 + row < E) pf_l2(e + (size_t)(t * 128 + row) * H + part);
    }
    CP_WAIT0(); __syncthreads();
    convert_bn(sm);
    __syncthreads();

    while (t < nTiles) {
        int nxt = t + gridDim.x;
        if (nxt < nTiles) stage_A(sb, g_epre, nxt * 128, E);
        // warm L2 with next tile's e rows during this tile's GEMM/epilogue
        if (nxt < nTiles) {
            int row = tid >> 2, part = (tid & 3) * 32;
            if (nxt * 128 + row < E) pf_l2(e + (size_t)(nxt * 128 + row) * H + part);
        }

        float C[8][4];
        gemm_compute(sb + SM_A, sb + SM_B, C);

        int e0 = t * 128;
#pragma unroll
        for (int nf = 0; nf < 8; nf++) {
#pragma unroll
            for (int hf = 0; hf < 2; hf++) {
                int ei = e0 + rm + hf * 8 + r_in;
                if (ei < E) {
                    int col = cn + nf * 8 + c2;
                    float2 ev = *(const float2*)(e + (size_t)ei * H + col);
                    float2 o = make_float2(ev.x + C[nf][2 * hf] + cv2[nf].x,
                                           ev.y + C[nf][2 * hf + 1] + cv2[nf].y);
                    *(float2*)(out + (size_t)ei * H + col) = o;
                }
            }
        }
        CP_WAIT0();
        __syncthreads();
        if (nxt < nTiles) convert_bn(sm);
        __syncthreads();
        t = nxt;
    }
}

// ---------------------------------------------------------------------------
__global__ void k_nstats(int rows) {
    int tid = threadIdx.x;
    int cg = tid & 31, wr = tid >> 5;
    float4 s = make_float4(0.f, 0.f, 0.f, 0.f);
    float4 qq = make_float4(0.f, 0.f, 0.f, 0.f);
    const float4* s4 = (const float4*)g_rowpack;
    for (int r = blockIdx.x * 8 + wr; r < rows; r += gridDim.x * 8) {
        float4 x = s4[(size_t)r * 64 + 32 + cg];
        s.x += x.x; s.y += x.y; s.z += x.z; s.w += x.w;
        qq.x += x.x * x.x; qq.y += x.y * x.y; qq.z += x.z * x.z; qq.w += x.w * x.w;
    }
    __shared__ float sh1[8][128], sh2[8][128];
    *(float4*)&sh1[wr][cg * 4] = s;
    *(float4*)&sh2[wr][cg * 4] = qq;
    __syncthreads();
    if (tid < 128) {
        float a = 0.f, b = 0.f;
#pragma unroll
        for (int ww = 0; ww < 8; ww++) { a += sh1[ww][tid]; b += sh2[ww][tid]; }
        atomicAdd(&g_stats[tid], a);
        atomicAdd(&g_stats[H + tid], b);
    }
}

// ---------------------------------------------------------------------------
__global__ void k_finalize(const float* __restrict__ gh, const float* __restrict__ bh,
                           const float* __restrict__ ge, const float* __restrict__ be,
                           int V, int E) {
    int j = threadIdx.x;
    float invV = 1.0f / (float)V, invE = 1.0f / (float)E;
    float mh = g_stats[j] * invV;
    float vh = g_stats[H + j] * invV - mh * mh;
    float sc = gh[j] * rsqrtf(vh + 1e-5f);
    g_scale_h[j] = sc;
    g_shift_h[j] = bh[j] - mh * sc;
    float me = g_stats[2 * H + j] * invE;
    float ve = g_stats[3 * H + j] * invE - me * me;
    float se = ge[j] * rsqrtf(ve + 1e-5f);
    g_scale_e[j] = se;
    g_shift_e[j] = be[j] - me * se;
}

// ---------------------------------------------------------------------------
__global__ void k_nodeout(const float* __restrict__ h, float* __restrict__ out, int V) {
    int idx = blockIdx.x * blockDim.x + threadIdx.x;
    int total = V * (H / 4);
    if (idx >= total) return;
    int row = idx >> 5, cs = idx & 31;
    int j = cs * 4;
    float4 a  = *(const float4*)&g_rowpack[(size_t)row * 256 + 128 + j];
    float4 sc = *(const float4*)&g_scale_h[j];
    float4 sh = *(const float4*)&g_shift_h[j];
    float4 hv = *(const float4*)&h[(size_t)idx * 4];
    float4 r;
    r.x = hv.x + fmaxf(fmaf(a.x, sc.x, sh.x), 0.f);
    r.y = hv.y + fmaxf(fmaf(a.y, sc.y, sh.y), 0.f);
    r.z = hv.z + fmaxf(fmaf(a.z, sc.z, sh.z), 0.f);
    r.w = hv.w + fmaxf(fmaf(a.w, sc.w, sh.w), 0.f);
    *(float4*)&out[(size_t)idx * 4] = r;
}

// ---------------------------------------------------------------------------
extern "C" void kernel_launch(void* const* d_in, const int* in_sizes, int n_in,
                              void* d_out, int out_size) {
    const float* h        = (const float*)d_in[0];
    const float* e        = (const float*)d_in[1];
    const float* time_emb = (const float*)d_in[2];
    const int*   eidx     = (const int*)d_in[3];
    const float* WU = (const float*)d_in[4];  const float* bU = (const float*)d_in[5];
    const float* WV = (const float*)d_in[6];  const float* bV = (const float*)d_in[7];
    const float* WA = (const float*)d_in[8];  const float* bA = (const float*)d_in[9];
    const float* WB = (const float*)d_in[10]; const float* bB = (const float*)d_in[11];
    const float* WC = (const float*)d_in[12]; const float* bC = (const float*)d_in[13];
    const float* Wt = (const float*)d_in[14]; const float* bt = (const float*)d_in[15];
    const float* Wo = (const float*)d_in[16]; const float* bo = (const float*)d_in[17];
    const float* gh = (const float*)d_in[18]; const float* bh = (const float*)d_in[19];
    const float* ge = (const float*)d_in[20]; const float* be = (const float*)d_in[21];

    int V = in_sizes[0] / H;
    int E = in_sizes[3] / 2;

    float* xout = (float*)d_out;
    float* eout = xout + (size_t)V * H;

    cudaFuncSetAttribute(k_node,    cudaFuncAttributeMaxDynamicSharedMemorySize, SMEM_BYTES);
    cudaFuncSetAttribute(k_edge,    cudaFuncAttributeMaxDynamicSharedMemorySize, SMEM_BYTES);
    cudaFuncSetAttribute(k_edgeout, cudaFuncAttributeMaxDynamicSharedMemorySize, SMEM_BYTES);

    int vTiles = (V + 127) / 128;
    int eTiles = (E + 127) / 128;
    int gxNode = vTiles < 37 ? vTiles : 37;
    int gxEdge = eTiles < 148 ? eTiles : 148;

    k_init<<<1, 128>>>(time_emb, Wt, bt, Wo, bo);
    k_prep<<<6, 256>>>(WU, WV, WA, WB, WC, Wo);
    k_node<<<dim3(gxNode, 4), NT, SMEM_BYTES>>>(h, bU, bV, bA, bB, V, vTiles);
    k_edge<<<gxEdge, NT, SMEM_BYTES>>>(e, bC, eidx, E, eTiles);
    k_nstats<<<512, 256>>>(V);
    k_finalize<<<1, 128>>>(gh, bh, ge, be, V, E);
    k_nodeout<<<(V * (H / 4) + 255) / 256, 256>>>(h, xout, V);
    k_edgeout<<<gxEdge, NT, SMEM_BYTES>>>(e, eout, E, eTiles);
}